// round 1
// baseline (speedup 1.0000x reference)
#include <cuda_runtime.h>
#include <math.h>

#define NN 50000
#define DD 256
#define EE 800000
#define LL 3

// ---------------- device scratch (allocation-free rule: __device__ globals) ---
__device__ float g_q[NN * DD];
__device__ float g_k[NN * DD];
__device__ float g_v[NN * DD];
__device__ float g_s[NN * DD];
__device__ float g_agg[NN * DD];
__device__ float g_h[NN * DD];
__device__ float g_alpha[EE];
__device__ float g_m[NN];
__device__ float g_den[NN];
__device__ int   g_src[EE];
__device__ int   g_dst[EE];
__device__ int   g_is64;

// ---------------- edge-index dtype detection + normalization -----------------
__global__ void detect_idx_kernel(const int* __restrict__ ei) {
    if (threadIdx.x == 0 && blockIdx.x == 0) {
        int all_hi_zero = 1;
        for (int j = 0; j < 256; j++) {
            if (ei[2 * j + 1] != 0) { all_hi_zero = 0; break; }
        }
        g_is64 = all_hi_zero;  // int64 little-endian: (lo=val, hi=0) pairs
    }
}

__global__ void convert_idx_kernel(const int* __restrict__ ei) {
    int i = blockIdx.x * blockDim.x + threadIdx.x;
    if (i >= EE) return;
    if (g_is64) {
        g_src[i] = ei[2 * i];
        g_dst[i] = ei[2 * (EE + i)];
    } else {
        g_src[i] = ei[i];
        g_dst[i] = ei[EE + i];
    }
}

// ---------------- SGEMM: C[M,256] = A[M,256] @ W[256,256] + bias -------------
// BM=128, BN=128, BK=16; 256 threads; 8x8 register tile per thread.
#define GBM 128
#define GBN 128
#define GBK 16
#define AS_LD 132  // padded

__global__ __launch_bounds__(256) void sgemm_bias_kernel(
    const float* __restrict__ A, const float* __restrict__ W,
    const float* __restrict__ bias, float* __restrict__ C, int M)
{
    __shared__ float As[GBK][AS_LD];   // transposed A tile: As[k][m]
    __shared__ float Bs[GBK][GBN];     // Bs[k][n]

    const int tid = threadIdx.x;
    const int tx = tid & 15;   // n-group 0..15
    const int ty = tid >> 4;   // m-group 0..15
    const int bm = blockIdx.x * GBM;
    const int bn = blockIdx.y * GBN;

    float acc[2][2][4][4];
    #pragma unroll
    for (int h = 0; h < 2; h++)
        #pragma unroll
        for (int g = 0; g < 2; g++)
            #pragma unroll
            for (int a = 0; a < 4; a++)
                #pragma unroll
                for (int b = 0; b < 4; b++) acc[h][g][a][b] = 0.f;

    for (int kt = 0; kt < DD; kt += GBK) {
        // Load A tile (128 rows x 16 k) as 512 float4, 2 per thread; transpose into As.
        #pragma unroll
        for (int r = 0; r < 2; r++) {
            int lin = tid + r * 256;       // 0..511
            int row = lin >> 2;            // 0..127
            int k4  = lin & 3;             // float4 index within 16 k
            float4 av = make_float4(0.f, 0.f, 0.f, 0.f);
            int gr = bm + row;
            if (gr < M)
                av = *(const float4*)(A + (size_t)gr * DD + kt + k4 * 4);
            As[k4 * 4 + 0][row] = av.x;
            As[k4 * 4 + 1][row] = av.y;
            As[k4 * 4 + 2][row] = av.z;
            As[k4 * 4 + 3][row] = av.w;
        }
        // Load B tile (16 k x 128 n) as 512 float4, 2 per thread.
        #pragma unroll
        for (int r = 0; r < 2; r++) {
            int lin = tid + r * 256;
            int row = lin >> 5;            // 0..15
            int c4  = lin & 31;            // 0..31
            float4 bv = *(const float4*)(W + (size_t)(kt + row) * DD + bn + c4 * 4);
            *(float4*)(&Bs[row][c4 * 4]) = bv;
        }
        __syncthreads();

        #pragma unroll
        for (int k = 0; k < GBK; k++) {
            float4 a0 = *(const float4*)(&As[k][ty * 4]);
            float4 a1 = *(const float4*)(&As[k][64 + ty * 4]);
            float4 b0 = *(const float4*)(&Bs[k][tx * 4]);
            float4 b1 = *(const float4*)(&Bs[k][64 + tx * 4]);
            float ar[2][4] = {{a0.x, a0.y, a0.z, a0.w}, {a1.x, a1.y, a1.z, a1.w}};
            float br[2][4] = {{b0.x, b0.y, b0.z, b0.w}, {b1.x, b1.y, b1.z, b1.w}};
            #pragma unroll
            for (int h = 0; h < 2; h++)
                #pragma unroll
                for (int g = 0; g < 2; g++)
                    #pragma unroll
                    for (int a = 0; a < 4; a++)
                        #pragma unroll
                        for (int b = 0; b < 4; b++)
                            acc[h][g][a][b] += ar[h][a] * br[g][b];
        }
        __syncthreads();
    }

    // Store with bias.
    #pragma unroll
    for (int g = 0; g < 2; g++) {
        float4 bb = *(const float4*)(bias + bn + g * 64 + tx * 4);
        #pragma unroll
        for (int h = 0; h < 2; h++) {
            #pragma unroll
            for (int a = 0; a < 4; a++) {
                int gr = bm + h * 64 + ty * 4 + a;
                if (gr < M) {
                    float4 o;
                    o.x = acc[h][g][a][0] + bb.x;
                    o.y = acc[h][g][a][1] + bb.y;
                    o.z = acc[h][g][a][2] + bb.z;
                    o.w = acc[h][g][a][3] + bb.w;
                    *(float4*)(C + (size_t)gr * DD + bn + g * 64 + tx * 4) = o;
                }
            }
        }
    }
}

// ---------------- per-layer init: agg=0, m=-inf, den=0 -----------------------
__global__ void init_kernel() {
    int i = blockIdx.x * blockDim.x + threadIdx.x;
    if (i < NN * DD) g_agg[i] = 0.f;
    if (i < NN) { g_m[i] = -INFINITY; g_den[i] = 0.f; }
}

// ---------------- float atomic max via int/uint trick -------------------------
__device__ __forceinline__ void atomicMaxFloat(float* addr, float val) {
    if (signbit(val))
        atomicMin((unsigned int*)addr, __float_as_uint(val));
    else
        atomicMax((int*)addr, __float_as_int(val));
}

// ---------------- edge kernels ------------------------------------------------
// warp per edge: alpha = (q[dst] . k[src]) / 16; fused segment-max
__global__ __launch_bounds__(256) void edge_alpha_kernel() {
    int w = (blockIdx.x * blockDim.x + threadIdx.x) >> 5;
    int lane = threadIdx.x & 31;
    if (w >= EE) return;
    int s = g_src[w], d = g_dst[w];
    const float4* q4 = (const float4*)g_q + (size_t)d * 64;
    const float4* k4 = (const float4*)g_k + (size_t)s * 64;
    float p = 0.f;
    #pragma unroll
    for (int i = 0; i < 2; i++) {
        float4 a = q4[lane + 32 * i];
        float4 b = k4[lane + 32 * i];
        p += a.x * b.x + a.y * b.y + a.z * b.z + a.w * b.w;
    }
    #pragma unroll
    for (int o = 16; o; o >>= 1) p += __shfl_xor_sync(0xffffffffu, p, o);
    if (lane == 0) {
        p *= 0.0625f;  // 1/sqrt(256)
        g_alpha[w] = p;
        atomicMaxFloat(&g_m[d], p);
    }
}

// thread per edge: e = exp(alpha - m[dst]); den[dst] += e
__global__ void edge_exp_kernel() {
    int i = blockIdx.x * blockDim.x + threadIdx.x;
    if (i >= EE) return;
    int d = g_dst[i];
    float e = expf(g_alpha[i] - g_m[d]);
    g_alpha[i] = e;
    atomicAdd(&g_den[d], e);
}

// warp per edge: agg[dst] += (e/den[dst]) * v[src]
__global__ __launch_bounds__(256) void edge_agg_kernel() {
    int w = (blockIdx.x * blockDim.x + threadIdx.x) >> 5;
    int lane = threadIdx.x & 31;
    if (w >= EE) return;
    int s = g_src[w], d = g_dst[w];
    float attn = g_alpha[w] / (g_den[d] + 1e-16f);
    const float4* v4 = (const float4*)g_v + (size_t)s * 64;
    float* aggrow = g_agg + (size_t)d * DD;
    #pragma unroll
    for (int i = 0; i < 2; i++) {
        int idx = lane + 32 * i;
        float4 vv = v4[idx];
        atomicAdd(&aggrow[idx * 4 + 0], attn * vv.x);
        atomicAdd(&aggrow[idx * 4 + 1], attn * vv.y);
        atomicAdd(&aggrow[idx * 4 + 2], attn * vv.z);
        atomicAdd(&aggrow[idx * 4 + 3], attn * vv.w);
    }
}

// ---------------- combine: out = relu?(agg + skip) ----------------------------
__global__ void combine_kernel(float* __restrict__ out, int do_relu) {
    int i = blockIdx.x * blockDim.x + threadIdx.x;
    if (i >= NN * DD) return;
    float vout = g_agg[i] + g_s[i];
    if (do_relu) vout = fmaxf(vout, 0.f);
    out[i] = vout;
}

// ---------------- launch ------------------------------------------------------
extern "C" void kernel_launch(void* const* d_in, const int* in_sizes, int n_in,
                              void* d_out, int out_size) {
    const float* x  = (const float*)d_in[0];
    const int*   ei = (const int*)d_in[1];
    const float* Wq = (const float*)d_in[2];
    const float* bq = (const float*)d_in[3];
    const float* Wk = (const float*)d_in[4];
    const float* bk = (const float*)d_in[5];
    const float* Wv = (const float*)d_in[6];
    const float* bv = (const float*)d_in[7];
    const float* Ws = (const float*)d_in[8];
    const float* bs = (const float*)d_in[9];
    float* out = (float*)d_out;

    float *q, *k, *v, *s, *h;
    cudaGetSymbolAddress((void**)&q, g_q);
    cudaGetSymbolAddress((void**)&k, g_k);
    cudaGetSymbolAddress((void**)&v, g_v);
    cudaGetSymbolAddress((void**)&s, g_s);
    cudaGetSymbolAddress((void**)&h, g_h);

    detect_idx_kernel<<<1, 32>>>(ei);
    convert_idx_kernel<<<(EE + 255) / 256, 256>>>(ei);

    dim3 ggrid((NN + GBM - 1) / GBM, DD / GBN);
    int nd_blocks   = (NN * DD + 255) / 256;
    int ew_blocks   = (EE * 32 + 255) / 256;   // warp per edge
    int et_blocks   = (EE + 255) / 256;        // thread per edge

    for (int l = 0; l < LL; l++) {
        const float* hin = (l == 0) ? x : h;
        size_t wo = (size_t)l * DD * DD;
        size_t bo = (size_t)l * DD;
        sgemm_bias_kernel<<<ggrid, 256>>>(hin, Wq + wo, bq + bo, q, NN);
        sgemm_bias_kernel<<<ggrid, 256>>>(hin, Wk + wo, bk + bo, k, NN);
        sgemm_bias_kernel<<<ggrid, 256>>>(hin, Wv + wo, bv + bo, v, NN);
        sgemm_bias_kernel<<<ggrid, 256>>>(hin, Ws + wo, bs + bo, s, NN);

        init_kernel<<<nd_blocks, 256>>>();
        edge_alpha_kernel<<<ew_blocks, 256>>>();
        edge_exp_kernel<<<et_blocks, 256>>>();
        edge_agg_kernel<<<ew_blocks, 256>>>();

        combine_kernel<<<nd_blocks, 256>>>((l == LL - 1) ? out : h, (l < LL - 1) ? 1 : 0);
    }
}

// round 3
// speedup vs baseline: 1.5175x; 1.5175x over previous
#include <cuda_runtime.h>
#include <math.h>

#define NN 50000
#define DD 256
#define EE 800000
#define LL 3

// ---------------- device scratch ---------------------------------------------
__device__ float g_q[NN * DD];
__device__ float g_k[NN * DD];
__device__ float g_v[NN * DD];
__device__ float g_s[NN * DD];
__device__ float g_h[NN * DD];
__device__ int   g_src[EE];
__device__ int   g_dst[EE];
__device__ int   g_esrc[EE];
__device__ int   g_deg[NN];      // degree, then reused as scatter cursor
__device__ int   g_off[NN + 1];
__device__ int   g_is64;

// ---------------- edge-index dtype detection ---------------------------------
__global__ void detect_idx_kernel(const int* __restrict__ ei) {
    if (threadIdx.x == 0 && blockIdx.x == 0) {
        int all_hi_zero = 1;
        for (int j = 0; j < 256; j++) {
            if (ei[2 * j + 1] != 0) { all_hi_zero = 0; break; }
        }
        g_is64 = all_hi_zero;  // int64 little-endian: (lo, hi=0) pairs
    }
}

__global__ void zero_deg_kernel() {
    int i = blockIdx.x * blockDim.x + threadIdx.x;
    if (i < NN) g_deg[i] = 0;
}

// convert indices + degree histogram
__global__ void convert_hist_kernel(const int* __restrict__ ei) {
    int i = blockIdx.x * blockDim.x + threadIdx.x;
    if (i >= EE) return;
    int s, d;
    if (g_is64) { s = ei[2 * i]; d = ei[2 * (EE + i)]; }
    else        { s = ei[i];     d = ei[EE + i]; }
    g_src[i] = s;
    g_dst[i] = d;
    atomicAdd(&g_deg[d], 1);
}

// single-block exclusive scan over degrees -> offsets; zero cursor
#define SCAN_T 1024
__global__ __launch_bounds__(SCAN_T) void scan_kernel() {
    __shared__ int ssum[SCAN_T];
    int t = threadIdx.x;
    const int chunk = (NN + SCAN_T - 1) / SCAN_T;
    int b = t * chunk;
    int e = min(b + chunk, NN);
    int s = 0;
    for (int i = b; i < e; i++) s += g_deg[i];
    ssum[t] = s;
    __syncthreads();
    for (int off = 1; off < SCAN_T; off <<= 1) {
        int v = (t >= off) ? ssum[t - off] : 0;
        __syncthreads();
        ssum[t] += v;
        __syncthreads();
    }
    int run = (t == 0) ? 0 : ssum[t - 1];
    for (int i = b; i < e; i++) { g_off[i] = run; run += g_deg[i]; }
    if (t == SCAN_T - 1) g_off[NN] = run;
    for (int i = b; i < e; i++) g_deg[i] = 0;  // cursor reset
}

__global__ void scatter_kernel() {
    int i = blockIdx.x * blockDim.x + threadIdx.x;
    if (i >= EE) return;
    int d = g_dst[i];
    int pos = g_off[d] + atomicAdd(&g_deg[d], 1);
    g_esrc[pos] = g_src[i];
}

// ---------------- SGEMM: C[M,256] = A[M,256] @ W[256,256] + bias -------------
#define GBM 128
#define GBN 128
#define GBK 16
#define AS_LD 132

__global__ __launch_bounds__(256) void sgemm_bias_kernel(
    const float* __restrict__ A, const float* __restrict__ W,
    const float* __restrict__ bias, float* __restrict__ C, int M)
{
    __shared__ float As[GBK][AS_LD];
    __shared__ float Bs[GBK][GBN];

    const int tid = threadIdx.x;
    const int tx = tid & 15;
    const int ty = tid >> 4;
    const int bm = blockIdx.x * GBM;
    const int bn = blockIdx.y * GBN;

    float acc[2][2][4][4];
    #pragma unroll
    for (int h = 0; h < 2; h++)
        #pragma unroll
        for (int g = 0; g < 2; g++)
            #pragma unroll
            for (int a = 0; a < 4; a++)
                #pragma unroll
                for (int b = 0; b < 4; b++) acc[h][g][a][b] = 0.f;

    for (int kt = 0; kt < DD; kt += GBK) {
        #pragma unroll
        for (int r = 0; r < 2; r++) {
            int lin = tid + r * 256;
            int row = lin >> 2;
            int k4  = lin & 3;
            float4 av = make_float4(0.f, 0.f, 0.f, 0.f);
            int gr = bm + row;
            if (gr < M)
                av = *(const float4*)(A + (size_t)gr * DD + kt + k4 * 4);
            As[k4 * 4 + 0][row] = av.x;
            As[k4 * 4 + 1][row] = av.y;
            As[k4 * 4 + 2][row] = av.z;
            As[k4 * 4 + 3][row] = av.w;
        }
        #pragma unroll
        for (int r = 0; r < 2; r++) {
            int lin = tid + r * 256;
            int row = lin >> 5;
            int c4  = lin & 31;
            float4 bv = *(const float4*)(W + (size_t)(kt + row) * DD + bn + c4 * 4);
            *(float4*)(&Bs[row][c4 * 4]) = bv;
        }
        __syncthreads();

        #pragma unroll
        for (int k = 0; k < GBK; k++) {
            float4 a0 = *(const float4*)(&As[k][ty * 4]);
            float4 a1 = *(const float4*)(&As[k][64 + ty * 4]);
            float4 b0 = *(const float4*)(&Bs[k][tx * 4]);
            float4 b1 = *(const float4*)(&Bs[k][64 + tx * 4]);
            float ar[2][4] = {{a0.x, a0.y, a0.z, a0.w}, {a1.x, a1.y, a1.z, a1.w}};
            float br[2][4] = {{b0.x, b0.y, b0.z, b0.w}, {b1.x, b1.y, b1.z, b1.w}};
            #pragma unroll
            for (int h = 0; h < 2; h++)
                #pragma unroll
                for (int g = 0; g < 2; g++)
                    #pragma unroll
                    for (int a = 0; a < 4; a++)
                        #pragma unroll
                        for (int b = 0; b < 4; b++)
                            acc[h][g][a][b] += ar[h][a] * br[g][b];
        }
        __syncthreads();
    }

    #pragma unroll
    for (int g = 0; g < 2; g++) {
        float4 bb = *(const float4*)(bias + bn + g * 64 + tx * 4);
        #pragma unroll
        for (int h = 0; h < 2; h++) {
            #pragma unroll
            for (int a = 0; a < 4; a++) {
                int gr = bm + h * 64 + ty * 4 + a;
                if (gr < M) {
                    float4 o;
                    o.x = acc[h][g][a][0] + bb.x;
                    o.y = acc[h][g][a][1] + bb.y;
                    o.z = acc[h][g][a][2] + bb.z;
                    o.w = acc[h][g][a][3] + bb.w;
                    *(float4*)(C + (size_t)gr * DD + bn + g * 64 + tx * 4) = o;
                }
            }
        }
    }
}

// ---------------- fused per-destination attention ----------------------------
// One warp per destination node. Logits + softmax + weighted aggregation + skip.
// Alphas cached in 4 regs/lane (deg <= 128); recompute fallback for larger deg.
__device__ __forceinline__ float warp_dot_qk(float4 qa, float4 qb, int s, int lane) {
    const float4* k4 = (const float4*)(g_k + (size_t)s * DD);
    float4 ka = __ldg(&k4[lane]);
    float4 kb = __ldg(&k4[lane + 32]);
    float p = qa.x * ka.x + qa.y * ka.y + qa.z * ka.z + qa.w * ka.w
            + qb.x * kb.x + qb.y * kb.y + qb.z * kb.z + qb.w * kb.w;
    #pragma unroll
    for (int o = 16; o; o >>= 1) p += __shfl_xor_sync(0xffffffffu, p, o);
    return p * 0.0625f;  // 1/sqrt(256)
}

__global__ __launch_bounds__(256) void dst_attn_kernel(float* __restrict__ out, int do_relu) {
    int d = (blockIdx.x * blockDim.x + threadIdx.x) >> 5;
    int lane = threadIdx.x & 31;
    if (d >= NN) return;

    int beg = g_off[d];
    int deg = g_off[d + 1] - beg;

    const float4* q4 = (const float4*)(g_q + (size_t)d * DD);
    float4 qa = q4[lane], qb = q4[lane + 32];

    float ar0 = 0.f, ar1 = 0.f, ar2 = 0.f, ar3 = 0.f;
    float mx = -INFINITY;
    bool small = (deg <= 128);

    // pass 1: logits + running max; cache alpha in regs (lane j&31, slot j>>5)
    for (int j = 0; j < deg; j++) {
        int s = __ldg(&g_esrc[beg + j]);
        float p = warp_dot_qk(qa, qb, s, lane);
        mx = fmaxf(mx, p);
        if (small && ((j & 31) == lane)) {
            int slot = j >> 5;
            if      (slot == 0) ar0 = p;
            else if (slot == 1) ar1 = p;
            else if (slot == 2) ar2 = p;
            else                ar3 = p;
        }
    }

    // pass 2: denominator
    float den = 0.f;
    if (small) {
        int t = 0;
        for (int j = lane; j < deg; j += 32, t++) {
            float a = (t == 0) ? ar0 : (t == 1) ? ar1 : (t == 2) ? ar2 : ar3;
            den += __expf(a - mx);
        }
        #pragma unroll
        for (int o = 16; o; o >>= 1) den += __shfl_xor_sync(0xffffffffu, den, o);
    } else {
        for (int j = 0; j < deg; j++) {
            int s = __ldg(&g_esrc[beg + j]);
            float p = warp_dot_qk(qa, qb, s, lane);
            den += (lane == 0) ? __expf(p - mx) : 0.f;
        }
        den = __shfl_sync(0xffffffffu, den, 0);
    }
    float invden = 1.0f / (den + 1e-16f);

    // pass 3: weighted aggregation of v[src]
    float4 acca = make_float4(0.f, 0.f, 0.f, 0.f);
    float4 accb = make_float4(0.f, 0.f, 0.f, 0.f);
    for (int j = 0; j < deg; j++) {
        float a;
        if (small) {
            int slot = j >> 5;
            float av = (slot == 0) ? ar0 : (slot == 1) ? ar1 : (slot == 2) ? ar2 : ar3;
            a = __shfl_sync(0xffffffffu, av, j & 31);
        } else {
            int s0 = __ldg(&g_esrc[beg + j]);
            a = warp_dot_qk(qa, qb, s0, lane);
        }
        float attn = __expf(a - mx) * invden;
        int s = __ldg(&g_esrc[beg + j]);
        const float4* v4 = (const float4*)(g_v + (size_t)s * DD);
        float4 va = __ldg(&v4[lane]);
        float4 vb = __ldg(&v4[lane + 32]);
        acca.x += attn * va.x; acca.y += attn * va.y;
        acca.z += attn * va.z; acca.w += attn * va.w;
        accb.x += attn * vb.x; accb.y += attn * vb.y;
        accb.z += attn * vb.z; accb.w += attn * vb.w;
    }

    // skip connection + optional relu, write out
    const float4* s4 = (const float4*)(g_s + (size_t)d * DD);
    float4 sa = s4[lane], sb = s4[lane + 32];
    float4 oa, ob;
    oa.x = acca.x + sa.x; oa.y = acca.y + sa.y;
    oa.z = acca.z + sa.z; oa.w = acca.w + sa.w;
    ob.x = accb.x + sb.x; ob.y = accb.y + sb.y;
    ob.z = accb.z + sb.z; ob.w = accb.w + sb.w;
    if (do_relu) {
        oa.x = fmaxf(oa.x, 0.f); oa.y = fmaxf(oa.y, 0.f);
        oa.z = fmaxf(oa.z, 0.f); oa.w = fmaxf(oa.w, 0.f);
        ob.x = fmaxf(ob.x, 0.f); ob.y = fmaxf(ob.y, 0.f);
        ob.z = fmaxf(ob.z, 0.f); ob.w = fmaxf(ob.w, 0.f);
    }
    float4* o4 = (float4*)(out + (size_t)d * DD);
    o4[lane] = oa;
    o4[lane + 32] = ob;
}

// ---------------- launch ------------------------------------------------------
extern "C" void kernel_launch(void* const* d_in, const int* in_sizes, int n_in,
                              void* d_out, int out_size) {
    const float* x  = (const float*)d_in[0];
    const int*   ei = (const int*)d_in[1];
    const float* Wq = (const float*)d_in[2];
    const float* bq = (const float*)d_in[3];
    const float* Wk = (const float*)d_in[4];
    const float* bk = (const float*)d_in[5];
    const float* Wv = (const float*)d_in[6];
    const float* bv = (const float*)d_in[7];
    const float* Ws = (const float*)d_in[8];
    const float* bs = (const float*)d_in[9];
    float* out = (float*)d_out;

    float *q, *k, *v, *s, *h;
    cudaGetSymbolAddress((void**)&q, g_q);
    cudaGetSymbolAddress((void**)&k, g_k);
    cudaGetSymbolAddress((void**)&v, g_v);
    cudaGetSymbolAddress((void**)&s, g_s);
    cudaGetSymbolAddress((void**)&h, g_h);

    // CSR build
    detect_idx_kernel<<<1, 32>>>(ei);
    zero_deg_kernel<<<(NN + 255) / 256, 256>>>();
    convert_hist_kernel<<<(EE + 255) / 256, 256>>>(ei);
    scan_kernel<<<1, SCAN_T>>>();
    scatter_kernel<<<(EE + 255) / 256, 256>>>();

    dim3 ggrid((NN + GBM - 1) / GBM, DD / GBN);
    int attn_blocks = (NN * 32 + 255) / 256;  // warp per dst node

    for (int l = 0; l < LL; l++) {
        const float* hin = (l == 0) ? x : h;
        size_t wo = (size_t)l * DD * DD;
        size_t bo = (size_t)l * DD;
        sgemm_bias_kernel<<<ggrid, 256>>>(hin, Wq + wo, bq + bo, q, NN);
        sgemm_bias_kernel<<<ggrid, 256>>>(hin, Wk + wo, bk + bo, k, NN);
        sgemm_bias_kernel<<<ggrid, 256>>>(hin, Wv + wo, bv + bo, v, NN);
        sgemm_bias_kernel<<<ggrid, 256>>>(hin, Ws + wo, bs + bo, s, NN);

        dst_attn_kernel<<<attn_blocks, 256>>>((l == LL - 1) ? out : h, (l < LL - 1) ? 1 : 0);
    }
}

// round 6
// speedup vs baseline: 2.0130x; 1.3265x over previous
#include <cuda_runtime.h>
#include <cuda_bf16.h>
#include <mma.h>
#include <math.h>
#include <stdint.h>

using namespace nvcuda;

#define NN 50000
#define DD 256
#define EE 800000
#define LL 3

// ---------------- device scratch ---------------------------------------------
__device__ float g_q[NN * DD];
__device__ float g_k[NN * DD];
__device__ float g_v[NN * DD];
__device__ float g_s[NN * DD];
__device__ float g_h[NN * DD];
__device__ __nv_bfloat16 g_wthi[12 * DD * DD];   // [mat][n][k] transposed + split
__device__ __nv_bfloat16 g_wtlo[12 * DD * DD];
__device__ int   g_src[EE];
__device__ int   g_dst[EE];
__device__ int   g_esrc[EE];
__device__ int   g_deg[NN];
__device__ int   g_off[NN + 1];
__device__ int   g_bsum[256];
__device__ int   g_is64;

// ---------------- edge-index dtype detection + CSR -----------------------------
__global__ void detect_idx_kernel(const int* __restrict__ ei) {
    if (threadIdx.x == 0 && blockIdx.x == 0) {
        int all_hi_zero = 1;
        for (int j = 0; j < 256; j++)
            if (ei[2 * j + 1] != 0) { all_hi_zero = 0; break; }
        g_is64 = all_hi_zero;
    }
}
__global__ void zero_deg_kernel() {
    int i = blockIdx.x * blockDim.x + threadIdx.x;
    if (i < NN) g_deg[i] = 0;
}
__global__ void convert_hist_kernel(const int* __restrict__ ei) {
    int i = blockIdx.x * blockDim.x + threadIdx.x;
    if (i >= EE) return;
    int s, d;
    if (g_is64) { s = ei[2 * i]; d = ei[2 * (EE + i)]; }
    else        { s = ei[i];     d = ei[EE + i]; }
    g_src[i] = s; g_dst[i] = d;
    atomicAdd(&g_deg[d], 1);
}
#define SCAN_NB 196
__global__ __launch_bounds__(256) void scan1_kernel() {
    __shared__ int sh[256];
    int i = blockIdx.x * 256 + threadIdx.x;
    int v = (i < NN) ? g_deg[i] : 0;
    sh[threadIdx.x] = v;
    __syncthreads();
    for (int o = 128; o; o >>= 1) {
        if (threadIdx.x < o) sh[threadIdx.x] += sh[threadIdx.x + o];
        __syncthreads();
    }
    if (threadIdx.x == 0) g_bsum[blockIdx.x] = sh[0];
}
__global__ __launch_bounds__(256) void scan2_kernel() {
    __shared__ int sh[256];
    int t = threadIdx.x;
    sh[t] = (t < SCAN_NB) ? g_bsum[t] : 0;
    __syncthreads();
    for (int o = 1; o < 256; o <<= 1) {
        int v = (t >= o) ? sh[t - o] : 0;
        __syncthreads();
        sh[t] += v;
        __syncthreads();
    }
    if (t < SCAN_NB) g_bsum[t] = (t == 0) ? 0 : sh[t - 1];
    if (t == 0) g_off[NN] = EE;
}
__global__ __launch_bounds__(256) void scan3_kernel() {
    __shared__ int sh[256];
    int i = blockIdx.x * 256 + threadIdx.x;
    int t = threadIdx.x;
    int v = (i < NN) ? g_deg[i] : 0;
    sh[t] = v;
    __syncthreads();
    for (int o = 1; o < 256; o <<= 1) {
        int u = (t >= o) ? sh[t - o] : 0;
        __syncthreads();
        sh[t] += u;
        __syncthreads();
    }
    if (i < NN) {
        g_off[i] = g_bsum[blockIdx.x] + sh[t] - v;
        g_deg[i] = 0;
    }
}
__global__ void scatter_kernel() {
    int i = blockIdx.x * blockDim.x + threadIdx.x;
    if (i >= EE) return;
    int d = g_dst[i];
    int pos = g_off[d] + atomicAdd(&g_deg[d], 1);
    g_esrc[pos] = g_src[i];
}

// ---------------- weight transpose + bf16 split --------------------------------
// g_wthi[m][n][k] = bf16(W[k][n]); g_wtlo[m][n][k] = bf16(W[k][n] - hi)
__global__ __launch_bounds__(256) void wsplit_kernel(
    const float* __restrict__ Wq, const float* __restrict__ Wk,
    const float* __restrict__ Wv, const float* __restrict__ Ws)
{
    __shared__ float t[32][33];
    int m = blockIdx.z;
    int l = m >> 2, wi = m & 3;
    const float* W = ((wi == 0) ? Wq : (wi == 1) ? Wk : (wi == 2) ? Wv : Ws) + (size_t)l * DD * DD;
    int k0 = blockIdx.y * 32, n0 = blockIdx.x * 32;
    #pragma unroll
    for (int r = 0; r < 32; r += 8) {
        int k = k0 + threadIdx.y + r, n = n0 + threadIdx.x;
        t[threadIdx.y + r][threadIdx.x] = W[k * DD + n];
    }
    __syncthreads();
    __nv_bfloat16* ohi = g_wthi + (size_t)m * DD * DD;
    __nv_bfloat16* olo = g_wtlo + (size_t)m * DD * DD;
    #pragma unroll
    for (int r = 0; r < 32; r += 8) {
        int n = n0 + threadIdx.y + r, k = k0 + threadIdx.x;
        float x = t[threadIdx.x][threadIdx.y + r];
        __nv_bfloat16 hi = __float2bfloat16(x);
        __nv_bfloat16 lo = __float2bfloat16(x - __bfloat162float(hi));
        ohi[n * DD + k] = hi;
        olo[n * DD + k] = lo;
    }
}

// ---------------- bf16x3 WMMA GEMM ---------------------------------------------
// C[M,256] = A[M,256] @ W + bias, one launch does Q,K,V,S via blockIdx.z.
// CTA: 128(M) x 128(N), BK=64. 8 warps, each 64x32 (4x2 wmma tiles).
#define APITCH 72
#define GEMM_SMEM 73728
// smem byte offsets (bf16 tiles)
#define SA_HI 0
#define SA_LO 18432
#define SB_HI 36864
#define SB_LO 55296

__global__ __launch_bounds__(256, 2) void bf16x3_gemm_kernel(
    const float* __restrict__ A, int layer,
    const float* __restrict__ bq, const float* __restrict__ bk,
    const float* __restrict__ bv, const float* __restrict__ bs, int M)
{
    extern __shared__ char smem[];
    __nv_bfloat16* Ahi = (__nv_bfloat16*)(smem + SA_HI);
    __nv_bfloat16* Alo = (__nv_bfloat16*)(smem + SA_LO);
    __nv_bfloat16* Bhi = (__nv_bfloat16*)(smem + SB_HI);
    __nv_bfloat16* Blo = (__nv_bfloat16*)(smem + SB_LO);

    const int tid = threadIdx.x;
    const int wid = tid >> 5;
    const int wm = wid >> 2;          // 0..1 (64 rows each)
    const int wn = wid & 3;           // 0..3 (32 cols each)
    const int bm = blockIdx.x * 128;
    const int bn = blockIdx.y * 128;
    const int z  = blockIdx.z;        // 0=q 1=k 2=v 3=s

    const int mat = layer * 4 + z;
    const __nv_bfloat16* Whi = g_wthi + (size_t)mat * DD * DD;
    const __nv_bfloat16* Wlo = g_wtlo + (size_t)mat * DD * DD;

    wmma::fragment<wmma::accumulator, 16, 16, 16, float> c[4][2];
    #pragma unroll
    for (int i = 0; i < 4; i++)
        #pragma unroll
        for (int j = 0; j < 2; j++) wmma::fill_fragment(c[i][j], 0.f);

    for (int ck = 0; ck < 4; ck++) {
        // A chunk: 128 rows x 64 floats -> bf16 hi/lo
        #pragma unroll
        for (int it = 0; it < 8; it++) {
            int idx = tid + it * 256;           // 0..2047
            int row = idx >> 4, q4 = idx & 15;
            float4 av = make_float4(0.f, 0.f, 0.f, 0.f);
            if (bm + row < M)
                av = __ldg((const float4*)(A + (size_t)(bm + row) * DD + ck * 64 + q4 * 4));
            __nv_bfloat16 h0 = __float2bfloat16(av.x);
            __nv_bfloat16 h1 = __float2bfloat16(av.y);
            __nv_bfloat16 h2 = __float2bfloat16(av.z);
            __nv_bfloat16 h3 = __float2bfloat16(av.w);
            __nv_bfloat16 l0 = __float2bfloat16(av.x - __bfloat162float(h0));
            __nv_bfloat16 l1 = __float2bfloat16(av.y - __bfloat162float(h1));
            __nv_bfloat16 l2 = __float2bfloat16(av.z - __bfloat162float(h2));
            __nv_bfloat16 l3 = __float2bfloat16(av.w - __bfloat162float(h3));
            __nv_bfloat162* dh = (__nv_bfloat162*)(Ahi + row * APITCH + q4 * 4);
            dh[0] = __halves2bfloat162(h0, h1);
            dh[1] = __halves2bfloat162(h2, h3);
            __nv_bfloat162* dl = (__nv_bfloat162*)(Alo + row * APITCH + q4 * 4);
            dl[0] = __halves2bfloat162(l0, l1);
            dl[1] = __halves2bfloat162(l2, l3);
        }
        // B chunk: 128 n-rows x 64 k bf16 (pre-split global)
        #pragma unroll
        for (int it = 0; it < 4; it++) {
            int idx = tid + it * 256;           // 0..1023
            int row = idx >> 3, s8 = idx & 7;
            uint4 bh = __ldg((const uint4*)(Whi + (size_t)(bn + row) * DD + ck * 64 + s8 * 8));
            uint4 bl = __ldg((const uint4*)(Wlo + (size_t)(bn + row) * DD + ck * 64 + s8 * 8));
            *(uint4*)(Bhi + row * APITCH + s8 * 8) = bh;
            *(uint4*)(Blo + row * APITCH + s8 * 8) = bl;
        }
        __syncthreads();

        #pragma unroll
        for (int pass = 0; pass < 3; pass++) {
            const __nv_bfloat16* As = (pass < 2) ? Ahi : Alo;
            const __nv_bfloat16* Bs = (pass == 1) ? Blo : Bhi;
            #pragma unroll
            for (int kk = 0; kk < 4; kk++) {
                wmma::fragment<wmma::matrix_a, 16, 16, 16, __nv_bfloat16, wmma::row_major> af[4];
                wmma::fragment<wmma::matrix_b, 16, 16, 16, __nv_bfloat16, wmma::col_major> bf[2];
                #pragma unroll
                for (int i = 0; i < 4; i++)
                    wmma::load_matrix_sync(af[i], As + (wm * 64 + i * 16) * APITCH + kk * 16, APITCH);
                #pragma unroll
                for (int j = 0; j < 2; j++)
                    wmma::load_matrix_sync(bf[j], Bs + (wn * 32 + j * 16) * APITCH + kk * 16, APITCH);
                #pragma unroll
                for (int i = 0; i < 4; i++)
                    #pragma unroll
                    for (int j = 0; j < 2; j++)
                        wmma::mma_sync(c[i][j], af[i], bf[j], c[i][j]);
            }
        }
        __syncthreads();
    }

    // stage accumulators to smem (reuse tile memory), then coalesced store + bias
    float* stage = (float*)smem;   // 128 x 132 pitch
    #pragma unroll
    for (int i = 0; i < 4; i++)
        #pragma unroll
        for (int j = 0; j < 2; j++)
            wmma::store_matrix_sync(stage + (wm * 64 + i * 16) * 132 + wn * 32 + j * 16,
                                    c[i][j], 132, wmma::mem_row_major);
    __syncthreads();

    const float* bias = ((z == 0) ? bq : (z == 1) ? bk : (z == 2) ? bv : bs);
    float* outp = (z == 0) ? g_q : (z == 1) ? g_k : (z == 2) ? g_v : g_s;

    #pragma unroll
    for (int it = 0; it < 16; it++) {
        int idx = tid + it * 256;               // 0..4095
        int row = idx >> 5, c4 = idx & 31;
        int gr = bm + row;
        if (gr < M) {
            float4 vv = *(float4*)(stage + row * 132 + c4 * 4);
            float4 bb = __ldg((const float4*)(bias + bn + c4 * 4));
            vv.x += bb.x; vv.y += bb.y; vv.z += bb.z; vv.w += bb.w;
            *(float4*)(outp + (size_t)gr * DD + bn + c4 * 4) = vv;
        }
    }
}

// ---------------- fused per-destination attention ------------------------------
__device__ __forceinline__ float warp_dot_qk(float4 qa, float4 qb, int s, int lane) {
    const float4* k4 = (const float4*)(g_k + (size_t)s * DD);
    float4 ka = __ldg(&k4[lane]);
    float4 kb = __ldg(&k4[lane + 32]);
    float p = qa.x * ka.x + qa.y * ka.y + qa.z * ka.z + qa.w * ka.w
            + qb.x * kb.x + qb.y * kb.y + qb.z * kb.z + qb.w * kb.w;
    #pragma unroll
    for (int o = 16; o; o >>= 1) p += __shfl_xor_sync(0xffffffffu, p, o);
    return p * 0.0625f;
}

__global__ __launch_bounds__(256) void dst_attn_kernel(float* __restrict__ out, int do_relu) {
    int d = (blockIdx.x * blockDim.x + threadIdx.x) >> 5;
    int lane = threadIdx.x & 31;
    if (d >= NN) return;

    int beg = g_off[d];
    int deg = g_off[d + 1] - beg;

    const float4* q4 = (const float4*)(g_q + (size_t)d * DD);
    float4 qa = q4[lane], qb = q4[lane + 32];

    float ar0 = 0.f, ar1 = 0.f, ar2 = 0.f, ar3 = 0.f;
    float mx = -INFINITY;
    bool small = (deg <= 128);

    for (int j = 0; j < deg; j++) {
        int s = __ldg(&g_esrc[beg + j]);
        float p = warp_dot_qk(qa, qb, s, lane);
        mx = fmaxf(mx, p);
        if (small && ((j & 31) == lane)) {
            int slot = j >> 5;
            if      (slot == 0) ar0 = p;
            else if (slot == 1) ar1 = p;
            else if (slot == 2) ar2 = p;
            else                ar3 = p;
        }
    }

    float den = 0.f;
    if (small) {
        int t = 0;
        for (int j = lane; j < deg; j += 32, t++) {
            float a = (t == 0) ? ar0 : (t == 1) ? ar1 : (t == 2) ? ar2 : ar3;
            den += __expf(a - mx);
        }
        #pragma unroll
        for (int o = 16; o; o >>= 1) den += __shfl_xor_sync(0xffffffffu, den, o);
    } else {
        for (int j = 0; j < deg; j++) {
            int s = __ldg(&g_esrc[beg + j]);
            float p = warp_dot_qk(qa, qb, s, lane);
            den += (lane == 0) ? __expf(p - mx) : 0.f;
        }
        den = __shfl_sync(0xffffffffu, den, 0);
    }
    float invden = 1.0f / (den + 1e-16f);

    float4 acca = make_float4(0.f, 0.f, 0.f, 0.f);
    float4 accb = make_float4(0.f, 0.f, 0.f, 0.f);
    for (int j = 0; j < deg; j++) {
        float a;
        if (small) {
            int slot = j >> 5;
            float av = (slot == 0) ? ar0 : (slot == 1) ? ar1 : (slot == 2) ? ar2 : ar3;
            a = __shfl_sync(0xffffffffu, av, j & 31);
        } else {
            int s0 = __ldg(&g_esrc[beg + j]);
            a = warp_dot_qk(qa, qb, s0, lane);
        }
        float attn = __expf(a - mx) * invden;
        int s = __ldg(&g_esrc[beg + j]);
        const float4* v4 = (const float4*)(g_v + (size_t)s * DD);
        float4 va = __ldg(&v4[lane]);
        float4 vb = __ldg(&v4[lane + 32]);
        acca.x += attn * va.x; acca.y += attn * va.y;
        acca.z += attn * va.z; acca.w += attn * va.w;
        accb.x += attn * vb.x; accb.y += attn * vb.y;
        accb.z += attn * vb.z; accb.w += attn * vb.w;
    }

    const float4* s4 = (const float4*)(g_s + (size_t)d * DD);
    float4 sa = s4[lane], sb = s4[lane + 32];
    float4 oa, ob;
    oa.x = acca.x + sa.x; oa.y = acca.y + sa.y;
    oa.z = acca.z + sa.z; oa.w = acca.w + sa.w;
    ob.x = accb.x + sb.x; ob.y = accb.y + sb.y;
    ob.z = accb.z + sb.z; ob.w = accb.w + sb.w;
    if (do_relu) {
        oa.x = fmaxf(oa.x, 0.f); oa.y = fmaxf(oa.y, 0.f);
        oa.z = fmaxf(oa.z, 0.f); oa.w = fmaxf(oa.w, 0.f);
        ob.x = fmaxf(ob.x, 0.f); ob.y = fmaxf(ob.y, 0.f);
        ob.z = fmaxf(ob.z, 0.f); ob.w = fmaxf(ob.w, 0.f);
    }
    float4* o4 = (float4*)(out + (size_t)d * DD);
    o4[lane] = oa;
    o4[lane + 32] = ob;
}

// ---------------- launch --------------------------------------------------------
extern "C" void kernel_launch(void* const* d_in, const int* in_sizes, int n_in,
                              void* d_out, int out_size) {
    const float* x  = (const float*)d_in[0];
    const int*   ei = (const int*)d_in[1];
    const float* Wq = (const float*)d_in[2];
    const float* bq = (const float*)d_in[3];
    const float* Wk = (const float*)d_in[4];
    const float* bk = (const float*)d_in[5];
    const float* Wv = (const float*)d_in[6];
    const float* bv = (const float*)d_in[7];
    const float* Ws = (const float*)d_in[8];
    const float* bs = (const float*)d_in[9];
    float* out = (float*)d_out;

    float* h;
    cudaGetSymbolAddress((void**)&h, g_h);

    cudaFuncSetAttribute(bf16x3_gemm_kernel,
                         cudaFuncAttributeMaxDynamicSharedMemorySize, GEMM_SMEM);

    // weight transpose + bf16 split (once per launch)
    wsplit_kernel<<<dim3(8, 8, 12), dim3(32, 8)>>>(Wq, Wk, Wv, Ws);

    // CSR build
    detect_idx_kernel<<<1, 32>>>(ei);
    zero_deg_kernel<<<(NN + 255) / 256, 256>>>();
    convert_hist_kernel<<<(EE + 255) / 256, 256>>>(ei);
    scan1_kernel<<<SCAN_NB, 256>>>();
    scan2_kernel<<<1, 256>>>();
    scan3_kernel<<<SCAN_NB, 256>>>();
    scatter_kernel<<<(EE + 255) / 256, 256>>>();

    dim3 ggrid((NN + 127) / 128, 2, 4);     // M-tiles x N-tiles x {q,k,v,s}
    int attn_blocks = (NN * 32 + 255) / 256;

    for (int l = 0; l < LL; l++) {
        const float* hin = (l == 0) ? x : h;
        size_t bo = (size_t)l * DD;
        bf16x3_gemm_kernel<<<ggrid, 256, GEMM_SMEM>>>(
            hin, l, bq + bo, bk + bo, bv + bo, bs + bo, NN);
        dst_attn_kernel<<<attn_blocks, 256>>>((l == LL - 1) ? out : h, (l < LL - 1) ? 1 : 0);
    }
}

// round 7
// speedup vs baseline: 2.0137x; 1.0003x over previous
#include <cuda_runtime.h>
#include <cuda_bf16.h>
#include <mma.h>
#include <math.h>
#include <stdint.h>

using namespace nvcuda;

#define NN 50000
#define DD 256
#define EE 800000
#define LL 3

// ---------------- device scratch ---------------------------------------------
__device__ float g_q[NN * DD];
__device__ float g_k[NN * DD];
__device__ float g_v[NN * DD];
__device__ float g_s[NN * DD];
__device__ float g_h[NN * DD];
__device__ __nv_bfloat16 g_wthi[12 * DD * DD];   // [mat][n][k] transposed + split
__device__ __nv_bfloat16 g_wtlo[12 * DD * DD];
__device__ int   g_src[EE];
__device__ int   g_dst[EE];
__device__ int   g_esrc[EE];
__device__ int   g_deg[NN];
__device__ int   g_off[NN + 1];
__device__ int   g_bsum[256];
__device__ int   g_is64;

// ---------------- edge-index dtype detection + CSR -----------------------------
__global__ void detect_idx_kernel(const int* __restrict__ ei) {
    if (threadIdx.x == 0 && blockIdx.x == 0) {
        int all_hi_zero = 1;
        for (int j = 0; j < 256; j++)
            if (ei[2 * j + 1] != 0) { all_hi_zero = 0; break; }
        g_is64 = all_hi_zero;
    }
}
__global__ void zero_deg_kernel() {
    int i = blockIdx.x * blockDim.x + threadIdx.x;
    if (i < NN) g_deg[i] = 0;
}
__global__ void convert_hist_kernel(const int* __restrict__ ei) {
    int i = blockIdx.x * blockDim.x + threadIdx.x;
    if (i >= EE) return;
    int s, d;
    if (g_is64) { s = ei[2 * i]; d = ei[2 * (EE + i)]; }
    else        { s = ei[i];     d = ei[EE + i]; }
    g_src[i] = s; g_dst[i] = d;
    atomicAdd(&g_deg[d], 1);
}
#define SCAN_NB 196
__global__ __launch_bounds__(256) void scan1_kernel() {
    __shared__ int sh[256];
    int i = blockIdx.x * 256 + threadIdx.x;
    int v = (i < NN) ? g_deg[i] : 0;
    sh[threadIdx.x] = v;
    __syncthreads();
    for (int o = 128; o; o >>= 1) {
        if (threadIdx.x < o) sh[threadIdx.x] += sh[threadIdx.x + o];
        __syncthreads();
    }
    if (threadIdx.x == 0) g_bsum[blockIdx.x] = sh[0];
}
__global__ __launch_bounds__(256) void scan2_kernel() {
    __shared__ int sh[256];
    int t = threadIdx.x;
    sh[t] = (t < SCAN_NB) ? g_bsum[t] : 0;
    __syncthreads();
    for (int o = 1; o < 256; o <<= 1) {
        int v = (t >= o) ? sh[t - o] : 0;
        __syncthreads();
        sh[t] += v;
        __syncthreads();
    }
    if (t < SCAN_NB) g_bsum[t] = (t == 0) ? 0 : sh[t - 1];
    if (t == 0) g_off[NN] = EE;
}
__global__ __launch_bounds__(256) void scan3_kernel() {
    __shared__ int sh[256];
    int i = blockIdx.x * 256 + threadIdx.x;
    int t = threadIdx.x;
    int v = (i < NN) ? g_deg[i] : 0;
    sh[t] = v;
    __syncthreads();
    for (int o = 1; o < 256; o <<= 1) {
        int u = (t >= o) ? sh[t - o] : 0;
        __syncthreads();
        sh[t] += u;
        __syncthreads();
    }
    if (i < NN) {
        g_off[i] = g_bsum[blockIdx.x] + sh[t] - v;
        g_deg[i] = 0;
    }
}
__global__ void scatter_kernel() {
    int i = blockIdx.x * blockDim.x + threadIdx.x;
    if (i >= EE) return;
    int d = g_dst[i];
    int pos = g_off[d] + atomicAdd(&g_deg[d], 1);
    g_esrc[pos] = g_src[i];
}

// ---------------- weight transpose + bf16 split --------------------------------
// g_wthi[m][n][k] = bf16(W[k][n]); g_wtlo[m][n][k] = bf16(W[k][n] - hi)
__global__ __launch_bounds__(256) void wsplit_kernel(
    const float* __restrict__ Wq, const float* __restrict__ Wk,
    const float* __restrict__ Wv, const float* __restrict__ Ws)
{
    __shared__ float t[32][33];
    int m = blockIdx.z;
    int l = m >> 2, wi = m & 3;
    const float* W = ((wi == 0) ? Wq : (wi == 1) ? Wk : (wi == 2) ? Wv : Ws) + (size_t)l * DD * DD;
    int k0 = blockIdx.y * 32, n0 = blockIdx.x * 32;
    #pragma unroll
    for (int r = 0; r < 32; r += 8) {
        int k = k0 + threadIdx.y + r, n = n0 + threadIdx.x;
        t[threadIdx.y + r][threadIdx.x] = W[k * DD + n];
    }
    __syncthreads();
    __nv_bfloat16* ohi = g_wthi + (size_t)m * DD * DD;
    __nv_bfloat16* olo = g_wtlo + (size_t)m * DD * DD;
    #pragma unroll
    for (int r = 0; r < 32; r += 8) {
        int n = n0 + threadIdx.y + r, k = k0 + threadIdx.x;
        float x = t[threadIdx.x][threadIdx.y + r];
        __nv_bfloat16 hi = __float2bfloat16(x);
        __nv_bfloat16 lo = __float2bfloat16(x - __bfloat162float(hi));
        ohi[n * DD + k] = hi;
        olo[n * DD + k] = lo;
    }
}

// ---------------- bf16x3 WMMA GEMM ---------------------------------------------
// C[M,256] = A[M,256] @ W + bias, one launch does Q,K,V,S via blockIdx.z.
// CTA: 128(M) x 128(N), BK=64. 8 warps, each 64x32 (4x2 wmma tiles).
#define APITCH 72
#define GEMM_SMEM 73728
// smem byte offsets (bf16 tiles)
#define SA_HI 0
#define SA_LO 18432
#define SB_HI 36864
#define SB_LO 55296

__global__ __launch_bounds__(256, 2) void bf16x3_gemm_kernel(
    const float* __restrict__ A, int layer,
    const float* __restrict__ bq, const float* __restrict__ bk,
    const float* __restrict__ bv, const float* __restrict__ bs, int M)
{
    extern __shared__ char smem[];
    __nv_bfloat16* Ahi = (__nv_bfloat16*)(smem + SA_HI);
    __nv_bfloat16* Alo = (__nv_bfloat16*)(smem + SA_LO);
    __nv_bfloat16* Bhi = (__nv_bfloat16*)(smem + SB_HI);
    __nv_bfloat16* Blo = (__nv_bfloat16*)(smem + SB_LO);

    const int tid = threadIdx.x;
    const int wid = tid >> 5;
    const int wm = wid >> 2;          // 0..1 (64 rows each)
    const int wn = wid & 3;           // 0..3 (32 cols each)
    const int bm = blockIdx.x * 128;
    const int bn = blockIdx.y * 128;
    const int z  = blockIdx.z;        // 0=q 1=k 2=v 3=s

    const int mat = layer * 4 + z;
    const __nv_bfloat16* Whi = g_wthi + (size_t)mat * DD * DD;
    const __nv_bfloat16* Wlo = g_wtlo + (size_t)mat * DD * DD;

    wmma::fragment<wmma::accumulator, 16, 16, 16, float> c[4][2];
    #pragma unroll
    for (int i = 0; i < 4; i++)
        #pragma unroll
        for (int j = 0; j < 2; j++) wmma::fill_fragment(c[i][j], 0.f);

    for (int ck = 0; ck < 4; ck++) {
        // A chunk: 128 rows x 64 floats -> bf16 hi/lo
        #pragma unroll
        for (int it = 0; it < 8; it++) {
            int idx = tid + it * 256;           // 0..2047
            int row = idx >> 4, q4 = idx & 15;
            float4 av = make_float4(0.f, 0.f, 0.f, 0.f);
            if (bm + row < M)
                av = __ldg((const float4*)(A + (size_t)(bm + row) * DD + ck * 64 + q4 * 4));
            __nv_bfloat16 h0 = __float2bfloat16(av.x);
            __nv_bfloat16 h1 = __float2bfloat16(av.y);
            __nv_bfloat16 h2 = __float2bfloat16(av.z);
            __nv_bfloat16 h3 = __float2bfloat16(av.w);
            __nv_bfloat16 l0 = __float2bfloat16(av.x - __bfloat162float(h0));
            __nv_bfloat16 l1 = __float2bfloat16(av.y - __bfloat162float(h1));
            __nv_bfloat16 l2 = __float2bfloat16(av.z - __bfloat162float(h2));
            __nv_bfloat16 l3 = __float2bfloat16(av.w - __bfloat162float(h3));
            __nv_bfloat162* dh = (__nv_bfloat162*)(Ahi + row * APITCH + q4 * 4);
            dh[0] = __halves2bfloat162(h0, h1);
            dh[1] = __halves2bfloat162(h2, h3);
            __nv_bfloat162* dl = (__nv_bfloat162*)(Alo + row * APITCH + q4 * 4);
            dl[0] = __halves2bfloat162(l0, l1);
            dl[1] = __halves2bfloat162(l2, l3);
        }
        // B chunk: 128 n-rows x 64 k bf16 (pre-split global)
        #pragma unroll
        for (int it = 0; it < 4; it++) {
            int idx = tid + it * 256;           // 0..1023
            int row = idx >> 3, s8 = idx & 7;
            uint4 bh = __ldg((const uint4*)(Whi + (size_t)(bn + row) * DD + ck * 64 + s8 * 8));
            uint4 bl = __ldg((const uint4*)(Wlo + (size_t)(bn + row) * DD + ck * 64 + s8 * 8));
            *(uint4*)(Bhi + row * APITCH + s8 * 8) = bh;
            *(uint4*)(Blo + row * APITCH + s8 * 8) = bl;
        }
        __syncthreads();

        #pragma unroll
        for (int pass = 0; pass < 3; pass++) {
            const __nv_bfloat16* As = (pass < 2) ? Ahi : Alo;
            const __nv_bfloat16* Bs = (pass == 1) ? Blo : Bhi;
            #pragma unroll
            for (int kk = 0; kk < 4; kk++) {
                wmma::fragment<wmma::matrix_a, 16, 16, 16, __nv_bfloat16, wmma::row_major> af[4];
                wmma::fragment<wmma::matrix_b, 16, 16, 16, __nv_bfloat16, wmma::col_major> bf[2];
                #pragma unroll
                for (int i = 0; i < 4; i++)
                    wmma::load_matrix_sync(af[i], As + (wm * 64 + i * 16) * APITCH + kk * 16, APITCH);
                #pragma unroll
                for (int j = 0; j < 2; j++)
                    wmma::load_matrix_sync(bf[j], Bs + (wn * 32 + j * 16) * APITCH + kk * 16, APITCH);
                #pragma unroll
                for (int i = 0; i < 4; i++)
                    #pragma unroll
                    for (int j = 0; j < 2; j++)
                        wmma::mma_sync(c[i][j], af[i], bf[j], c[i][j]);
            }
        }
        __syncthreads();
    }

    // stage accumulators to smem (reuse tile memory), then coalesced store + bias
    float* stage = (float*)smem;   // 128 x 132 pitch
    #pragma unroll
    for (int i = 0; i < 4; i++)
        #pragma unroll
        for (int j = 0; j < 2; j++)
            wmma::store_matrix_sync(stage + (wm * 64 + i * 16) * 132 + wn * 32 + j * 16,
                                    c[i][j], 132, wmma::mem_row_major);
    __syncthreads();

    const float* bias = ((z == 0) ? bq : (z == 1) ? bk : (z == 2) ? bv : bs);
    float* outp = (z == 0) ? g_q : (z == 1) ? g_k : (z == 2) ? g_v : g_s;

    #pragma unroll
    for (int it = 0; it < 16; it++) {
        int idx = tid + it * 256;               // 0..4095
        int row = idx >> 5, c4 = idx & 31;
        int gr = bm + row;
        if (gr < M) {
            float4 vv = *(float4*)(stage + row * 132 + c4 * 4);
            float4 bb = __ldg((const float4*)(bias + bn + c4 * 4));
            vv.x += bb.x; vv.y += bb.y; vv.z += bb.z; vv.w += bb.w;
            *(float4*)(outp + (size_t)gr * DD + bn + c4 * 4) = vv;
        }
    }
}

// ---------------- fused per-destination attention ------------------------------
__device__ __forceinline__ float warp_dot_qk(float4 qa, float4 qb, int s, int lane) {
    const float4* k4 = (const float4*)(g_k + (size_t)s * DD);
    float4 ka = __ldg(&k4[lane]);
    float4 kb = __ldg(&k4[lane + 32]);
    float p = qa.x * ka.x + qa.y * ka.y + qa.z * ka.z + qa.w * ka.w
            + qb.x * kb.x + qb.y * kb.y + qb.z * kb.z + qb.w * kb.w;
    #pragma unroll
    for (int o = 16; o; o >>= 1) p += __shfl_xor_sync(0xffffffffu, p, o);
    return p * 0.0625f;
}

__global__ __launch_bounds__(256) void dst_attn_kernel(float* __restrict__ out, int do_relu) {
    int d = (blockIdx.x * blockDim.x + threadIdx.x) >> 5;
    int lane = threadIdx.x & 31;
    if (d >= NN) return;

    int beg = g_off[d];
    int deg = g_off[d + 1] - beg;

    const float4* q4 = (const float4*)(g_q + (size_t)d * DD);
    float4 qa = q4[lane], qb = q4[lane + 32];

    float ar0 = 0.f, ar1 = 0.f, ar2 = 0.f, ar3 = 0.f;
    float mx = -INFINITY;
    bool small = (deg <= 128);

    for (int j = 0; j < deg; j++) {
        int s = __ldg(&g_esrc[beg + j]);
        float p = warp_dot_qk(qa, qb, s, lane);
        mx = fmaxf(mx, p);
        if (small && ((j & 31) == lane)) {
            int slot = j >> 5;
            if      (slot == 0) ar0 = p;
            else if (slot == 1) ar1 = p;
            else if (slot == 2) ar2 = p;
            else                ar3 = p;
        }
    }

    float den = 0.f;
    if (small) {
        int t = 0;
        for (int j = lane; j < deg; j += 32, t++) {
            float a = (t == 0) ? ar0 : (t == 1) ? ar1 : (t == 2) ? ar2 : ar3;
            den += __expf(a - mx);
        }
        #pragma unroll
        for (int o = 16; o; o >>= 1) den += __shfl_xor_sync(0xffffffffu, den, o);
    } else {
        for (int j = 0; j < deg; j++) {
            int s = __ldg(&g_esrc[beg + j]);
            float p = warp_dot_qk(qa, qb, s, lane);
            den += (lane == 0) ? __expf(p - mx) : 0.f;
        }
        den = __shfl_sync(0xffffffffu, den, 0);
    }
    float invden = 1.0f / (den + 1e-16f);

    float4 acca = make_float4(0.f, 0.f, 0.f, 0.f);
    float4 accb = make_float4(0.f, 0.f, 0.f, 0.f);
    for (int j = 0; j < deg; j++) {
        float a;
        if (small) {
            int slot = j >> 5;
            float av = (slot == 0) ? ar0 : (slot == 1) ? ar1 : (slot == 2) ? ar2 : ar3;
            a = __shfl_sync(0xffffffffu, av, j & 31);
        } else {
            int s0 = __ldg(&g_esrc[beg + j]);
            a = warp_dot_qk(qa, qb, s0, lane);
        }
        float attn = __expf(a - mx) * invden;
        int s = __ldg(&g_esrc[beg + j]);
        const float4* v4 = (const float4*)(g_v + (size_t)s * DD);
        float4 va = __ldg(&v4[lane]);
        float4 vb = __ldg(&v4[lane + 32]);
        acca.x += attn * va.x; acca.y += attn * va.y;
        acca.z += attn * va.z; acca.w += attn * va.w;
        accb.x += attn * vb.x; accb.y += attn * vb.y;
        accb.z += attn * vb.z; accb.w += attn * vb.w;
    }

    const float4* s4 = (const float4*)(g_s + (size_t)d * DD);
    float4 sa = s4[lane], sb = s4[lane + 32];
    float4 oa, ob;
    oa.x = acca.x + sa.x; oa.y = acca.y + sa.y;
    oa.z = acca.z + sa.z; oa.w = acca.w + sa.w;
    ob.x = accb.x + sb.x; ob.y = accb.y + sb.y;
    ob.z = accb.z + sb.z; ob.w = accb.w + sb.w;
    if (do_relu) {
        oa.x = fmaxf(oa.x, 0.f); oa.y = fmaxf(oa.y, 0.f);
        oa.z = fmaxf(oa.z, 0.f); oa.w = fmaxf(oa.w, 0.f);
        ob.x = fmaxf(ob.x, 0.f); ob.y = fmaxf(ob.y, 0.f);
        ob.z = fmaxf(ob.z, 0.f); ob.w = fmaxf(ob.w, 0.f);
    }
    float4* o4 = (float4*)(out + (size_t)d * DD);
    o4[lane] = oa;
    o4[lane + 32] = ob;
}

// ---------------- launch --------------------------------------------------------
extern "C" void kernel_launch(void* const* d_in, const int* in_sizes, int n_in,
                              void* d_out, int out_size) {
    const float* x  = (const float*)d_in[0];
    const int*   ei = (const int*)d_in[1];
    const float* Wq = (const float*)d_in[2];
    const float* bq = (const float*)d_in[3];
    const float* Wk = (const float*)d_in[4];
    const float* bk = (const float*)d_in[5];
    const float* Wv = (const float*)d_in[6];
    const float* bv = (const float*)d_in[7];
    const float* Ws = (const float*)d_in[8];
    const float* bs = (const float*)d_in[9];
    float* out = (float*)d_out;

    float* h;
    cudaGetSymbolAddress((void**)&h, g_h);

    cudaFuncSetAttribute(bf16x3_gemm_kernel,
                         cudaFuncAttributeMaxDynamicSharedMemorySize, GEMM_SMEM);

    // weight transpose + bf16 split (once per launch)
    wsplit_kernel<<<dim3(8, 8, 12), dim3(32, 8)>>>(Wq, Wk, Wv, Ws);

    // CSR build
    detect_idx_kernel<<<1, 32>>>(ei);
    zero_deg_kernel<<<(NN + 255) / 256, 256>>>();
    convert_hist_kernel<<<(EE + 255) / 256, 256>>>(ei);
    scan1_kernel<<<SCAN_NB, 256>>>();
    scan2_kernel<<<1, 256>>>();
    scan3_kernel<<<SCAN_NB, 256>>>();
    scatter_kernel<<<(EE + 255) / 256, 256>>>();

    dim3 ggrid((NN + 127) / 128, 2, 4);     // M-tiles x N-tiles x {q,k,v,s}
    int attn_blocks = (NN * 32 + 255) / 256;

    for (int l = 0; l < LL; l++) {
        const float* hin = (l == 0) ? x : h;
        size_t bo = (size_t)l * DD;
        bf16x3_gemm_kernel<<<ggrid, 256, GEMM_SMEM>>>(
            hin, l, bq + bo, bk + bo, bv + bo, bs + bo, NN);
        dst_attn_kernel<<<attn_blocks, 256>>>((l == LL - 1) ? out : h, (l < LL - 1) ? 1 : 0);
    }
}

// round 8
// speedup vs baseline: 2.3975x; 1.1906x over previous
#include <cuda_runtime.h>
#include <cuda_bf16.h>
#include <mma.h>
#include <math.h>
#include <stdint.h>

using namespace nvcuda;

#define NN 50000
#define DD 256
#define EE 800000
#define LL 3

// ---------------- device scratch ---------------------------------------------
__device__ float g_q[NN * DD];
__device__ float g_k[NN * DD];
__device__ float g_v[NN * DD];
__device__ float g_s[NN * DD];
__device__ float g_h[NN * DD];
__device__ __nv_bfloat16 g_ahi[NN * DD];         // layer input, bf16-split
__device__ __nv_bfloat16 g_alo[NN * DD];
__device__ __nv_bfloat16 g_wthi[12 * DD * DD];   // [mat][n][k] transposed + split
__device__ __nv_bfloat16 g_wtlo[12 * DD * DD];
__device__ int   g_src[EE];
__device__ int   g_dst[EE];
__device__ int   g_esrc[EE];
__device__ int   g_deg[NN];
__device__ int   g_off[NN + 1];
__device__ int   g_bsum[256];
__device__ int   g_is64;

// ---------------- cp.async helpers --------------------------------------------
__device__ __forceinline__ void cp_async16(uint32_t dst, const void* src) {
    asm volatile("cp.async.ca.shared.global [%0], [%1], 16;" :: "r"(dst), "l"(src));
}
__device__ __forceinline__ void cp_commit() {
    asm volatile("cp.async.commit_group;" ::: "memory");
}
template <int N>
__device__ __forceinline__ void cp_wait() {
    asm volatile("cp.async.wait_group %0;" :: "n"(N) : "memory");
}

// ---------------- edge-index dtype detection + CSR -----------------------------
__global__ void detect_idx_kernel(const int* __restrict__ ei) {
    if (threadIdx.x == 0 && blockIdx.x == 0) {
        int all_hi_zero = 1;
        for (int j = 0; j < 256; j++)
            if (ei[2 * j + 1] != 0) { all_hi_zero = 0; break; }
        g_is64 = all_hi_zero;
    }
}
__global__ void zero_deg_kernel() {
    int i = blockIdx.x * blockDim.x + threadIdx.x;
    if (i < NN) g_deg[i] = 0;
}
__global__ void convert_hist_kernel(const int* __restrict__ ei) {
    int i = blockIdx.x * blockDim.x + threadIdx.x;
    if (i >= EE) return;
    int s, d;
    if (g_is64) { s = ei[2 * i]; d = ei[2 * (EE + i)]; }
    else        { s = ei[i];     d = ei[EE + i]; }
    g_src[i] = s; g_dst[i] = d;
    atomicAdd(&g_deg[d], 1);
}
#define SCAN_NB 196
__global__ __launch_bounds__(256) void scan1_kernel() {
    __shared__ int sh[256];
    int i = blockIdx.x * 256 + threadIdx.x;
    int v = (i < NN) ? g_deg[i] : 0;
    sh[threadIdx.x] = v;
    __syncthreads();
    for (int o = 128; o; o >>= 1) {
        if (threadIdx.x < o) sh[threadIdx.x] += sh[threadIdx.x + o];
        __syncthreads();
    }
    if (threadIdx.x == 0) g_bsum[blockIdx.x] = sh[0];
}
__global__ __launch_bounds__(256) void scan2_kernel() {
    __shared__ int sh[256];
    int t = threadIdx.x;
    sh[t] = (t < SCAN_NB) ? g_bsum[t] : 0;
    __syncthreads();
    for (int o = 1; o < 256; o <<= 1) {
        int v = (t >= o) ? sh[t - o] : 0;
        __syncthreads();
        sh[t] += v;
        __syncthreads();
    }
    if (t < SCAN_NB) g_bsum[t] = (t == 0) ? 0 : sh[t - 1];
    if (t == 0) g_off[NN] = EE;
}
__global__ __launch_bounds__(256) void scan3_kernel() {
    __shared__ int sh[256];
    int i = blockIdx.x * 256 + threadIdx.x;
    int t = threadIdx.x;
    int v = (i < NN) ? g_deg[i] : 0;
    sh[t] = v;
    __syncthreads();
    for (int o = 1; o < 256; o <<= 1) {
        int u = (t >= o) ? sh[t - o] : 0;
        __syncthreads();
        sh[t] += u;
        __syncthreads();
    }
    if (i < NN) {
        g_off[i] = g_bsum[blockIdx.x] + sh[t] - v;
        g_deg[i] = 0;
    }
}
__global__ void scatter_kernel() {
    int i = blockIdx.x * blockDim.x + threadIdx.x;
    if (i >= EE) return;
    int d = g_dst[i];
    int pos = g_off[d] + atomicAdd(&g_deg[d], 1);
    g_esrc[pos] = g_src[i];
}

// ---------------- weight transpose + bf16 split --------------------------------
__global__ __launch_bounds__(256) void wsplit_kernel(
    const float* __restrict__ Wq, const float* __restrict__ Wk,
    const float* __restrict__ Wv, const float* __restrict__ Ws)
{
    __shared__ float t[32][33];
    int m = blockIdx.z;
    int l = m >> 2, wi = m & 3;
    const float* W = ((wi == 0) ? Wq : (wi == 1) ? Wk : (wi == 2) ? Wv : Ws) + (size_t)l * DD * DD;
    int k0 = blockIdx.y * 32, n0 = blockIdx.x * 32;
    #pragma unroll
    for (int r = 0; r < 32; r += 8) {
        int k = k0 + threadIdx.y + r, n = n0 + threadIdx.x;
        t[threadIdx.y + r][threadIdx.x] = W[k * DD + n];
    }
    __syncthreads();
    __nv_bfloat16* ohi = g_wthi + (size_t)m * DD * DD;
    __nv_bfloat16* olo = g_wtlo + (size_t)m * DD * DD;
    #pragma unroll
    for (int r = 0; r < 32; r += 8) {
        int n = n0 + threadIdx.y + r, k = k0 + threadIdx.x;
        float x = t[threadIdx.x][threadIdx.y + r];
        __nv_bfloat16 hi = __float2bfloat16(x);
        __nv_bfloat16 lo = __float2bfloat16(x - __bfloat162float(hi));
        ohi[n * DD + k] = hi;
        olo[n * DD + k] = lo;
    }
}

// ---------------- A split: fp32 -> bf16 hi/lo (per layer) ----------------------
__global__ __launch_bounds__(256) void asplit_kernel(const float* __restrict__ A) {
    int i = blockIdx.x * blockDim.x + threadIdx.x;   // float4 index
    if (i >= NN * DD / 4) return;
    float4 av = __ldg((const float4*)A + i);
    __nv_bfloat16 h0 = __float2bfloat16(av.x);
    __nv_bfloat16 h1 = __float2bfloat16(av.y);
    __nv_bfloat16 h2 = __float2bfloat16(av.z);
    __nv_bfloat16 h3 = __float2bfloat16(av.w);
    __nv_bfloat162 hl = __halves2bfloat162(h0, h1);
    __nv_bfloat162 hh = __halves2bfloat162(h2, h3);
    __nv_bfloat162 ll = __halves2bfloat162(
        __float2bfloat16(av.x - __bfloat162float(h0)),
        __float2bfloat16(av.y - __bfloat162float(h1)));
    __nv_bfloat162 lh = __halves2bfloat162(
        __float2bfloat16(av.z - __bfloat162float(h2)),
        __float2bfloat16(av.w - __bfloat162float(h3)));
    ((__nv_bfloat162*)g_ahi)[i * 2]     = hl;
    ((__nv_bfloat162*)g_ahi)[i * 2 + 1] = hh;
    ((__nv_bfloat162*)g_alo)[i * 2]     = ll;
    ((__nv_bfloat162*)g_alo)[i * 2 + 1] = lh;
}

// ---------------- bf16x3 WMMA GEMM, cp.async double-buffered -------------------
// C[M,256] = A[M,256] @ W + bias; blockIdx.z = {q,k,v,s}. CTA 128x128, BK=32.
#define APITCH 40                       // bf16 elems; row = 64B data in 80B pitch
#define TILE_SPLIT_B (128 * APITCH * 2) // 10240 bytes per split
#define STAGE_B (4 * TILE_SPLIT_B)      // Ahi,Alo,Bhi,Blo = 40960
#define GEMM_SMEM (2 * STAGE_B)         // 81920

__global__ __launch_bounds__(256, 2) void bf16x3_gemm_kernel(
    int layer,
    const float* __restrict__ bq, const float* __restrict__ bk,
    const float* __restrict__ bv, const float* __restrict__ bs, int M)
{
    extern __shared__ char smem[];
    const int tid = threadIdx.x;
    const int wid = tid >> 5;
    const int wm = wid >> 2;          // 0..1
    const int wn = wid & 3;           // 0..3
    const int bm = blockIdx.x * 128;
    const int bn = blockIdx.y * 128;
    const int z  = blockIdx.z;

    const int mat = layer * 4 + z;
    const __nv_bfloat16* Whi = g_wthi + (size_t)mat * DD * DD;
    const __nv_bfloat16* Wlo = g_wtlo + (size_t)mat * DD * DD;

    const uint32_t smem_base = (uint32_t)__cvta_generic_to_shared(smem);

    // per-thread cp.async assignments: 2048 16B segs per chunk / 256 thr = 8.
    // seg layout: [split(4)][row(128)][seg4(4)]  split: 0=Ahi 1=Alo 2=Bhi 3=Blo
    wmma::fragment<wmma::accumulator, 16, 16, 16, float> c[4][2];
    #pragma unroll
    for (int i = 0; i < 4; i++)
        #pragma unroll
        for (int j = 0; j < 2; j++) wmma::fill_fragment(c[i][j], 0.f);

    // issue loads for chunk ck into buffer buf
    auto load_chunk = [&](int ck, int buf) {
        uint32_t sb = smem_base + buf * STAGE_B;
        #pragma unroll
        for (int it = 0; it < 8; it++) {
            int seg = tid + it * 256;          // 0..2047
            int split = seg >> 9;              // 0..3
            int rem = seg & 511;
            int row = rem >> 2;                // 0..127
            int s4  = rem & 3;                 // 16B seg within 64B row
            uint32_t daddr = sb + split * TILE_SPLIT_B + (row * APITCH + s4 * 8) * 2;
            const __nv_bfloat16* gp;
            if (split == 0) {
                int gr = min(bm + row, M - 1);
                gp = g_ahi + (size_t)gr * DD + ck * 32 + s4 * 8;
            } else if (split == 1) {
                int gr = min(bm + row, M - 1);
                gp = g_alo + (size_t)gr * DD + ck * 32 + s4 * 8;
            } else if (split == 2) {
                gp = Whi + (size_t)(bn + row) * DD + ck * 32 + s4 * 8;
            } else {
                gp = Wlo + (size_t)(bn + row) * DD + ck * 32 + s4 * 8;
            }
            cp_async16(daddr, gp);
        }
        cp_commit();
    };

    load_chunk(0, 0);

    for (int ck = 0; ck < 8; ck++) {
        if (ck < 7) load_chunk(ck + 1, (ck + 1) & 1);
        if (ck < 7) cp_wait<1>(); else cp_wait<0>();
        __syncthreads();

        char* stg = smem + (ck & 1) * STAGE_B;
        __nv_bfloat16* Ahi = (__nv_bfloat16*)(stg);
        __nv_bfloat16* Alo = (__nv_bfloat16*)(stg + TILE_SPLIT_B);
        __nv_bfloat16* Bhi = (__nv_bfloat16*)(stg + 2 * TILE_SPLIT_B);
        __nv_bfloat16* Blo = (__nv_bfloat16*)(stg + 3 * TILE_SPLIT_B);

        #pragma unroll
        for (int pass = 0; pass < 3; pass++) {
            const __nv_bfloat16* As = (pass < 2) ? Ahi : Alo;
            const __nv_bfloat16* Bs = (pass == 1) ? Blo : Bhi;
            #pragma unroll
            for (int kk = 0; kk < 2; kk++) {
                wmma::fragment<wmma::matrix_a, 16, 16, 16, __nv_bfloat16, wmma::row_major> af[4];
                wmma::fragment<wmma::matrix_b, 16, 16, 16, __nv_bfloat16, wmma::col_major> bf[2];
                #pragma unroll
                for (int i = 0; i < 4; i++)
                    wmma::load_matrix_sync(af[i], As + (wm * 64 + i * 16) * APITCH + kk * 16, APITCH);
                #pragma unroll
                for (int j = 0; j < 2; j++)
                    wmma::load_matrix_sync(bf[j], Bs + (wn * 32 + j * 16) * APITCH + kk * 16, APITCH);
                #pragma unroll
                for (int i = 0; i < 4; i++)
                    #pragma unroll
                    for (int j = 0; j < 2; j++)
                        wmma::mma_sync(c[i][j], af[i], bf[j], c[i][j]);
            }
        }
        __syncthreads();
    }

    // epilogue: stage accumulators, coalesced store + bias
    float* stage = (float*)smem;   // 128 x 132
    #pragma unroll
    for (int i = 0; i < 4; i++)
        #pragma unroll
        for (int j = 0; j < 2; j++)
            wmma::store_matrix_sync(stage + (wm * 64 + i * 16) * 132 + wn * 32 + j * 16,
                                    c[i][j], 132, wmma::mem_row_major);
    __syncthreads();

    const float* bias = ((z == 0) ? bq : (z == 1) ? bk : (z == 2) ? bv : bs);
    float* outp = (z == 0) ? g_q : (z == 1) ? g_k : (z == 2) ? g_v : g_s;

    #pragma unroll
    for (int it = 0; it < 16; it++) {
        int idx = tid + it * 256;
        int row = idx >> 5, c4 = idx & 31;
        int gr = bm + row;
        if (gr < M) {
            float4 vv = *(float4*)(stage + row * 132 + c4 * 4);
            float4 bb = __ldg((const float4*)(bias + bn + c4 * 4));
            vv.x += bb.x; vv.y += bb.y; vv.z += bb.z; vv.w += bb.w;
            *(float4*)(outp + (size_t)gr * DD + bn + c4 * 4) = vv;
        }
    }
}

// ---------------- fused per-destination attention ------------------------------
__device__ __forceinline__ float warp_dot_qk(float4 qa, float4 qb, int s, int lane) {
    const float4* k4 = (const float4*)(g_k + (size_t)s * DD);
    float4 ka = __ldg(&k4[lane]);
    float4 kb = __ldg(&k4[lane + 32]);
    float p = qa.x * ka.x + qa.y * ka.y + qa.z * ka.z + qa.w * ka.w
            + qb.x * kb.x + qb.y * kb.y + qb.z * kb.z + qb.w * kb.w;
    #pragma unroll
    for (int o = 16; o; o >>= 1) p += __shfl_xor_sync(0xffffffffu, p, o);
    return p * 0.0625f;
}

__global__ __launch_bounds__(256) void dst_attn_kernel(float* __restrict__ out, int do_relu) {
    int d = (blockIdx.x * blockDim.x + threadIdx.x) >> 5;
    int lane = threadIdx.x & 31;
    if (d >= NN) return;

    int beg = g_off[d];
    int deg = g_off[d + 1] - beg;

    const float4* q4 = (const float4*)(g_q + (size_t)d * DD);
    float4 qa = q4[lane], qb = q4[lane + 32];

    float ar0 = 0.f, ar1 = 0.f, ar2 = 0.f, ar3 = 0.f;
    float mx = -INFINITY;
    bool small = (deg <= 128);

    for (int j = 0; j < deg; j++) {
        int s = __ldg(&g_esrc[beg + j]);
        float p = warp_dot_qk(qa, qb, s, lane);
        mx = fmaxf(mx, p);
        if (small && ((j & 31) == lane)) {
            int slot = j >> 5;
            if      (slot == 0) ar0 = p;
            else if (slot == 1) ar1 = p;
            else if (slot == 2) ar2 = p;
            else                ar3 = p;
        }
    }

    float den = 0.f;
    if (small) {
        int t = 0;
        for (int j = lane; j < deg; j += 32, t++) {
            float a = (t == 0) ? ar0 : (t == 1) ? ar1 : (t == 2) ? ar2 : ar3;
            den += __expf(a - mx);
        }
        #pragma unroll
        for (int o = 16; o; o >>= 1) den += __shfl_xor_sync(0xffffffffu, den, o);
    } else {
        for (int j = 0; j < deg; j++) {
            int s = __ldg(&g_esrc[beg + j]);
            float p = warp_dot_qk(qa, qb, s, lane);
            den += (lane == 0) ? __expf(p - mx) : 0.f;
        }
        den = __shfl_sync(0xffffffffu, den, 0);
    }
    float invden = 1.0f / (den + 1e-16f);

    float4 acca = make_float4(0.f, 0.f, 0.f, 0.f);
    float4 accb = make_float4(0.f, 0.f, 0.f, 0.f);
    for (int j = 0; j < deg; j++) {
        float a;
        if (small) {
            int slot = j >> 5;
            float av = (slot == 0) ? ar0 : (slot == 1) ? ar1 : (slot == 2) ? ar2 : ar3;
            a = __shfl_sync(0xffffffffu, av, j & 31);
        } else {
            int s0 = __ldg(&g_esrc[beg + j]);
            a = warp_dot_qk(qa, qb, s0, lane);
        }
        float attn = __expf(a - mx) * invden;
        int s = __ldg(&g_esrc[beg + j]);
        const float4* v4 = (const float4*)(g_v + (size_t)s * DD);
        float4 va = __ldg(&v4[lane]);
        float4 vb = __ldg(&v4[lane + 32]);
        acca.x += attn * va.x; acca.y += attn * va.y;
        acca.z += attn * va.z; acca.w += attn * va.w;
        accb.x += attn * vb.x; accb.y += attn * vb.y;
        accb.z += attn * vb.z; accb.w += attn * vb.w;
    }

    const float4* s4 = (const float4*)(g_s + (size_t)d * DD);
    float4 sa = s4[lane], sb = s4[lane + 32];
    float4 oa, ob;
    oa.x = acca.x + sa.x; oa.y = acca.y + sa.y;
    oa.z = acca.z + sa.z; oa.w = acca.w + sa.w;
    ob.x = accb.x + sb.x; ob.y = accb.y + sb.y;
    ob.z = accb.z + sb.z; ob.w = accb.w + sb.w;
    if (do_relu) {
        oa.x = fmaxf(oa.x, 0.f); oa.y = fmaxf(oa.y, 0.f);
        oa.z = fmaxf(oa.z, 0.f); oa.w = fmaxf(oa.w, 0.f);
        ob.x = fmaxf(ob.x, 0.f); ob.y = fmaxf(ob.y, 0.f);
        ob.z = fmaxf(ob.z, 0.f); ob.w = fmaxf(ob.w, 0.f);
    }
    float4* o4 = (float4*)(out + (size_t)d * DD);
    o4[lane] = oa;
    o4[lane + 32] = ob;
}

// ---------------- launch --------------------------------------------------------
extern "C" void kernel_launch(void* const* d_in, const int* in_sizes, int n_in,
                              void* d_out, int out_size) {
    const float* x  = (const float*)d_in[0];
    const int*   ei = (const int*)d_in[1];
    const float* Wq = (const float*)d_in[2];
    const float* bq = (const float*)d_in[3];
    const float* Wk = (const float*)d_in[4];
    const float* bk = (const float*)d_in[5];
    const float* Wv = (const float*)d_in[6];
    const float* bv = (const float*)d_in[7];
    const float* Ws = (const float*)d_in[8];
    const float* bs = (const float*)d_in[9];
    float* out = (float*)d_out;

    float* h;
    cudaGetSymbolAddress((void**)&h, g_h);

    cudaFuncSetAttribute(bf16x3_gemm_kernel,
                         cudaFuncAttributeMaxDynamicSharedMemorySize, GEMM_SMEM);

    wsplit_kernel<<<dim3(8, 8, 12), dim3(32, 8)>>>(Wq, Wk, Wv, Ws);

    detect_idx_kernel<<<1, 32>>>(ei);
    zero_deg_kernel<<<(NN + 255) / 256, 256>>>();
    convert_hist_kernel<<<(EE + 255) / 256, 256>>>(ei);
    scan1_kernel<<<SCAN_NB, 256>>>();
    scan2_kernel<<<1, 256>>>();
    scan3_kernel<<<SCAN_NB, 256>>>();
    scatter_kernel<<<(EE + 255) / 256, 256>>>();

    dim3 ggrid((NN + 127) / 128, 2, 4);
    int attn_blocks = (NN * 32 + 255) / 256;
    int split_blocks = (NN * DD / 4 + 255) / 256;

    for (int l = 0; l < LL; l++) {
        const float* hin = (l == 0) ? x : h;
        size_t bo = (size_t)l * DD;
        asplit_kernel<<<split_blocks, 256>>>(hin);
        bf16x3_gemm_kernel<<<ggrid, 256, GEMM_SMEM>>>(
            l, bq + bo, bk + bo, bv + bo, bs + bo, NN);
        dst_attn_kernel<<<attn_blocks, 256>>>((l == LL - 1) ? out : h, (l < LL - 1) ? 1 : 0);
    }
}

// round 11
// speedup vs baseline: 2.6438x; 1.1027x over previous
#include <cuda_runtime.h>
#include <cuda_bf16.h>
#include <mma.h>
#include <math.h>
#include <stdint.h>

using namespace nvcuda;

#define NN 50000
#define DD 256
#define EE 800000
#define LL 3

// ---------------- device scratch ---------------------------------------------
__device__ float g_q[NN * DD];
__device__ float g_k[NN * DD];
__device__ float g_v[NN * DD];
__device__ float g_s[NN * DD];
__device__ __nv_bfloat16 g_ahi[NN * DD];         // layer input, bf16-split
__device__ __nv_bfloat16 g_alo[NN * DD];
__device__ __nv_bfloat16 g_wthi[12 * DD * DD];   // [mat][n][k] transposed + split
__device__ __nv_bfloat16 g_wtlo[12 * DD * DD];
__device__ int   g_src[EE];
__device__ int   g_dst[EE];
__device__ int   g_esrc[EE];
__device__ int   g_deg[NN];
__device__ int   g_off[NN + 1];
__device__ int   g_bsum[256];
__device__ int   g_is64;

// ---------------- cp.async helpers --------------------------------------------
__device__ __forceinline__ void cp_async16(uint32_t dst, const void* src) {
    asm volatile("cp.async.cg.shared.global [%0], [%1], 16;" :: "r"(dst), "l"(src));
}
__device__ __forceinline__ void cp_commit() {
    asm volatile("cp.async.commit_group;" ::: "memory");
}
template <int N>
__device__ __forceinline__ void cp_wait() {
    asm volatile("cp.async.wait_group %0;" :: "n"(N) : "memory");
}

// ---------------- edge-index dtype detection + CSR -----------------------------
__global__ void detect_idx_kernel(const int* __restrict__ ei) {
    if (threadIdx.x == 0 && blockIdx.x == 0) {
        int all_hi_zero = 1;
        for (int j = 0; j < 256; j++)
            if (ei[2 * j + 1] != 0) { all_hi_zero = 0; break; }
        g_is64 = all_hi_zero;
    }
}
__global__ void zero_deg_kernel() {
    int i = blockIdx.x * blockDim.x + threadIdx.x;
    if (i < NN) g_deg[i] = 0;
}
__global__ void convert_hist_kernel(const int* __restrict__ ei) {
    int i = blockIdx.x * blockDim.x + threadIdx.x;
    if (i >= EE) return;
    int s, d;
    if (g_is64) { s = ei[2 * i]; d = ei[2 * (EE + i)]; }
    else        { s = ei[i];     d = ei[EE + i]; }
    g_src[i] = s; g_dst[i] = d;
    atomicAdd(&g_deg[d], 1);
}
#define SCAN_NB 196
__global__ __launch_bounds__(256) void scan1_kernel() {
    __shared__ int sh[256];
    int i = blockIdx.x * 256 + threadIdx.x;
    int v = (i < NN) ? g_deg[i] : 0;
    sh[threadIdx.x] = v;
    __syncthreads();
    for (int o = 128; o; o >>= 1) {
        if (threadIdx.x < o) sh[threadIdx.x] += sh[threadIdx.x + o];
        __syncthreads();
    }
    if (threadIdx.x == 0) g_bsum[blockIdx.x] = sh[0];
}
__global__ __launch_bounds__(256) void scan2_kernel() {
    __shared__ int sh[256];
    int t = threadIdx.x;
    sh[t] = (t < SCAN_NB) ? g_bsum[t] : 0;
    __syncthreads();
    for (int o = 1; o < 256; o <<= 1) {
        int v = (t >= o) ? sh[t - o] : 0;
        __syncthreads();
        sh[t] += v;
        __syncthreads();
    }
    if (t < SCAN_NB) g_bsum[t] = (t == 0) ? 0 : sh[t - 1];
    if (t == 0) g_off[NN] = EE;
}
__global__ __launch_bounds__(256) void scan3_kernel() {
    __shared__ int sh[256];
    int i = blockIdx.x * 256 + threadIdx.x;
    int t = threadIdx.x;
    int v = (i < NN) ? g_deg[i] : 0;
    sh[t] = v;
    __syncthreads();
    for (int o = 1; o < 256; o <<= 1) {
        int u = (t >= o) ? sh[t - o] : 0;
        __syncthreads();
        sh[t] += u;
        __syncthreads();
    }
    if (i < NN) {
        g_off[i] = g_bsum[blockIdx.x] + sh[t] - v;
        g_deg[i] = 0;
    }
}
__global__ void scatter_kernel() {
    int i = blockIdx.x * blockDim.x + threadIdx.x;
    if (i >= EE) return;
    int d = g_dst[i];
    int pos = g_off[d] + atomicAdd(&g_deg[d], 1);
    g_esrc[pos] = g_src[i];
}

// ---------------- weight transpose + bf16 split --------------------------------
__global__ __launch_bounds__(256) void wsplit_kernel(
    const float* __restrict__ Wq, const float* __restrict__ Wk,
    const float* __restrict__ Wv, const float* __restrict__ Ws)
{
    __shared__ float t[32][33];
    int m = blockIdx.z;
    int l = m >> 2, wi = m & 3;
    const float* W = ((wi == 0) ? Wq : (wi == 1) ? Wk : (wi == 2) ? Wv : Ws) + (size_t)l * DD * DD;
    int k0 = blockIdx.y * 32, n0 = blockIdx.x * 32;
    #pragma unroll
    for (int r = 0; r < 32; r += 8) {
        int k = k0 + threadIdx.y + r, n = n0 + threadIdx.x;
        t[threadIdx.y + r][threadIdx.x] = W[k * DD + n];
    }
    __syncthreads();
    __nv_bfloat16* ohi = g_wthi + (size_t)m * DD * DD;
    __nv_bfloat16* olo = g_wtlo + (size_t)m * DD * DD;
    #pragma unroll
    for (int r = 0; r < 32; r += 8) {
        int n = n0 + threadIdx.y + r, k = k0 + threadIdx.x;
        float x = t[threadIdx.x][threadIdx.y + r];
        __nv_bfloat16 hi = __float2bfloat16(x);
        __nv_bfloat16 lo = __float2bfloat16(x - __bfloat162float(hi));
        ohi[n * DD + k] = hi;
        olo[n * DD + k] = lo;
    }
}

// ---------------- A split for the layer-0 input x ------------------------------
__global__ __launch_bounds__(256) void asplit_kernel(const float* __restrict__ A) {
    int i = blockIdx.x * blockDim.x + threadIdx.x;   // float4 index
    if (i >= NN * DD / 4) return;
    float4 av = __ldg((const float4*)A + i);
    __nv_bfloat16 h0 = __float2bfloat16(av.x);
    __nv_bfloat16 h1 = __float2bfloat16(av.y);
    __nv_bfloat16 h2 = __float2bfloat16(av.z);
    __nv_bfloat16 h3 = __float2bfloat16(av.w);
    __nv_bfloat162 hl = __halves2bfloat162(h0, h1);
    __nv_bfloat162 hh = __halves2bfloat162(h2, h3);
    __nv_bfloat162 ll = __halves2bfloat162(
        __float2bfloat16(av.x - __bfloat162float(h0)),
        __float2bfloat16(av.y - __bfloat162float(h1)));
    __nv_bfloat162 lh = __halves2bfloat162(
        __float2bfloat16(av.z - __bfloat162float(h2)),
        __float2bfloat16(av.w - __bfloat162float(h3)));
    ((__nv_bfloat162*)g_ahi)[i * 2]     = hl;
    ((__nv_bfloat162*)g_ahi)[i * 2 + 1] = hh;
    ((__nv_bfloat162*)g_alo)[i * 2]     = ll;
    ((__nv_bfloat162*)g_alo)[i * 2 + 1] = lh;
}

// ---------------- bf16x3 WMMA GEMM, 2-stage cp.async pipeline ------------------
// C[M,256] = A[M,256] @ W + bias; blockIdx.z = {q,k,v,s}. CTA 128x128, BK=32.
#define APITCH 40                       // bf16 elems; 80B pitch (16B-aligned rows)
#define TILE_SPLIT_B (128 * APITCH * 2) // 10240 bytes per split
#define STAGE_B (4 * TILE_SPLIT_B)      // 40960
#define GEMM_SMEM (2 * STAGE_B)         // 81920 -> 2 CTAs/SM

__global__ __launch_bounds__(256, 2) void bf16x3_gemm_kernel(
    int layer,
    const float* __restrict__ bq, const float* __restrict__ bk,
    const float* __restrict__ bv, const float* __restrict__ bs, int M)
{
    extern __shared__ char smem[];
    const int tid = threadIdx.x;
    const int wid = tid >> 5;
    const int wm = wid >> 2;          // 0..1
    const int wn = wid & 3;           // 0..3
    const int bm = blockIdx.x * 128;
    const int bn = blockIdx.y * 128;
    const int z  = blockIdx.z;

    const int mat = layer * 4 + z;
    const __nv_bfloat16* Whi = g_wthi + (size_t)mat * DD * DD;
    const __nv_bfloat16* Wlo = g_wtlo + (size_t)mat * DD * DD;

    const uint32_t smem_base = (uint32_t)__cvta_generic_to_shared(smem);

    wmma::fragment<wmma::accumulator, 16, 16, 16, float> c[4][2];
    #pragma unroll
    for (int i = 0; i < 4; i++)
        #pragma unroll
        for (int j = 0; j < 2; j++) wmma::fill_fragment(c[i][j], 0.f);

    // 2048 16B segs per chunk / 256 threads = 8 cp.async each.
    auto load_chunk = [&](int ck, int buf) {
        uint32_t sb = smem_base + buf * STAGE_B;
        #pragma unroll
        for (int it = 0; it < 8; it++) {
            int seg = tid + it * 256;          // 0..2047
            int split = seg >> 9;              // 0=Ahi 1=Alo 2=Bhi 3=Blo
            int rem = seg & 511;
            int row = rem >> 2;                // 0..127
            int s4  = rem & 3;                 // 16B seg within 64B row
            uint32_t daddr = sb + split * TILE_SPLIT_B + (row * APITCH + s4 * 8) * 2;
            const __nv_bfloat16* gp;
            if (split == 0) {
                int gr = min(bm + row, M - 1);
                gp = g_ahi + (size_t)gr * DD + ck * 32 + s4 * 8;
            } else if (split == 1) {
                int gr = min(bm + row, M - 1);
                gp = g_alo + (size_t)gr * DD + ck * 32 + s4 * 8;
            } else if (split == 2) {
                gp = Whi + (size_t)(bn + row) * DD + ck * 32 + s4 * 8;
            } else {
                gp = Wlo + (size_t)(bn + row) * DD + ck * 32 + s4 * 8;
            }
            cp_async16(daddr, gp);
        }
        cp_commit();
    };

    load_chunk(0, 0);

    for (int ck = 0; ck < 8; ck++) {
        if (ck < 7) { load_chunk(ck + 1, (ck + 1) & 1); cp_wait<1>(); }
        else { cp_wait<0>(); }
        __syncthreads();

        char* stg = smem + (ck & 1) * STAGE_B;
        __nv_bfloat16* Ahi = (__nv_bfloat16*)(stg);
        __nv_bfloat16* Alo = (__nv_bfloat16*)(stg + TILE_SPLIT_B);
        __nv_bfloat16* Bhi = (__nv_bfloat16*)(stg + 2 * TILE_SPLIT_B);
        __nv_bfloat16* Blo = (__nv_bfloat16*)(stg + 3 * TILE_SPLIT_B);

        #pragma unroll
        for (int kk = 0; kk < 2; kk++) {
            wmma::fragment<wmma::matrix_b, 16, 16, 16, __nv_bfloat16, wmma::col_major> bH[2], bL[2];
            #pragma unroll
            for (int j = 0; j < 2; j++) {
                wmma::load_matrix_sync(bH[j], Bhi + (wn * 32 + j * 16) * APITCH + kk * 16, APITCH);
                wmma::load_matrix_sync(bL[j], Blo + (wn * 32 + j * 16) * APITCH + kk * 16, APITCH);
            }
            {
                wmma::fragment<wmma::matrix_a, 16, 16, 16, __nv_bfloat16, wmma::row_major> aH[4];
                #pragma unroll
                for (int i = 0; i < 4; i++)
                    wmma::load_matrix_sync(aH[i], Ahi + (wm * 64 + i * 16) * APITCH + kk * 16, APITCH);
                #pragma unroll
                for (int i = 0; i < 4; i++)
                    #pragma unroll
                    for (int j = 0; j < 2; j++) {
                        wmma::mma_sync(c[i][j], aH[i], bH[j], c[i][j]);
                        wmma::mma_sync(c[i][j], aH[i], bL[j], c[i][j]);
                    }
            }
            {
                wmma::fragment<wmma::matrix_a, 16, 16, 16, __nv_bfloat16, wmma::row_major> aL[4];
                #pragma unroll
                for (int i = 0; i < 4; i++)
                    wmma::load_matrix_sync(aL[i], Alo + (wm * 64 + i * 16) * APITCH + kk * 16, APITCH);
                #pragma unroll
                for (int i = 0; i < 4; i++)
                    #pragma unroll
                    for (int j = 0; j < 2; j++)
                        wmma::mma_sync(c[i][j], aL[i], bH[j], c[i][j]);
            }
        }
        __syncthreads();
    }

    // epilogue: stage accumulators, coalesced store + bias
    float* stage = (float*)smem;   // 128 x 132 floats = 67584B < GEMM_SMEM
    #pragma unroll
    for (int i = 0; i < 4; i++)
        #pragma unroll
        for (int j = 0; j < 2; j++)
            wmma::store_matrix_sync(stage + (wm * 64 + i * 16) * 132 + wn * 32 + j * 16,
                                    c[i][j], 132, wmma::mem_row_major);
    __syncthreads();

    const float* bias = ((z == 0) ? bq : (z == 1) ? bk : (z == 2) ? bv : bs);
    float* outp = (z == 0) ? g_q : (z == 1) ? g_k : (z == 2) ? g_v : g_s;

    #pragma unroll
    for (int it = 0; it < 16; it++) {
        int idx = tid + it * 256;
        int row = idx >> 5, c4 = idx & 31;
        int gr = bm + row;
        if (gr < M) {
            float4 vv = *(float4*)(stage + row * 132 + c4 * 4);
            float4 bb = __ldg((const float4*)(bias + bn + c4 * 4));
            vv.x += bb.x; vv.y += bb.y; vv.z += bb.z; vv.w += bb.w;
            *(float4*)(outp + (size_t)gr * DD + bn + c4 * 4) = vv;
        }
    }
}

// ---------------- fused per-destination attention ------------------------------
__device__ __forceinline__ float warp_dot_qk(float4 qa, float4 qb, int s, int lane) {
    const float4* k4 = (const float4*)(g_k + (size_t)s * DD);
    float4 ka = __ldg(&k4[lane]);
    float4 kb = __ldg(&k4[lane + 32]);
    float p = qa.x * ka.x + qa.y * ka.y + qa.z * ka.z + qa.w * ka.w
            + qb.x * kb.x + qb.y * kb.y + qb.z * kb.z + qb.w * kb.w;
    #pragma unroll
    for (int o = 16; o; o >>= 1) p += __shfl_xor_sync(0xffffffffu, p, o);
    return p * 0.0625f;
}

__device__ __forceinline__ void store_split4(int d, int col0, float4 r) {
    // relu already applied; write bf16 hi/lo for 4 consecutive cols
    __nv_bfloat16 h0 = __float2bfloat16(r.x);
    __nv_bfloat16 h1 = __float2bfloat16(r.y);
    __nv_bfloat16 h2 = __float2bfloat16(r.z);
    __nv_bfloat16 h3 = __float2bfloat16(r.w);
    __nv_bfloat162* dh = (__nv_bfloat162*)(g_ahi + (size_t)d * DD + col0);
    dh[0] = __halves2bfloat162(h0, h1);
    dh[1] = __halves2bfloat162(h2, h3);
    __nv_bfloat162* dl = (__nv_bfloat162*)(g_alo + (size_t)d * DD + col0);
    dl[0] = __halves2bfloat162(__float2bfloat16(r.x - __bfloat162float(h0)),
                               __float2bfloat16(r.y - __bfloat162float(h1)));
    dl[1] = __halves2bfloat162(__float2bfloat16(r.z - __bfloat162float(h2)),
                               __float2bfloat16(r.w - __bfloat162float(h3)));
}

// mode 1: intermediate layer -> relu + bf16 split store; mode 0: final -> fp32 out
__global__ __launch_bounds__(256) void dst_attn_kernel(float* __restrict__ out, int mode) {
    int d = (blockIdx.x * blockDim.x + threadIdx.x) >> 5;
    int lane = threadIdx.x & 31;
    if (d >= NN) return;

    int beg = g_off[d];
    int deg = g_off[d + 1] - beg;

    const float4* q4 = (const float4*)(g_q + (size_t)d * DD);
    float4 qa = q4[lane], qb = q4[lane + 32];

    float ar0 = 0.f, ar1 = 0.f, ar2 = 0.f, ar3 = 0.f;
    float mx = -INFINITY;
    bool small = (deg <= 128);

    for (int j = 0; j < deg; j++) {
        int s = __ldg(&g_esrc[beg + j]);
        float p = warp_dot_qk(qa, qb, s, lane);
        mx = fmaxf(mx, p);
        if (small && ((j & 31) == lane)) {
            int slot = j >> 5;
            if      (slot == 0) ar0 = p;
            else if (slot == 1) ar1 = p;
            else if (slot == 2) ar2 = p;
            else                ar3 = p;
        }
    }

    float den = 0.f;
    if (small) {
        int t = 0;
        for (int j = lane; j < deg; j += 32, t++) {
            float a = (t == 0) ? ar0 : (t == 1) ? ar1 : (t == 2) ? ar2 : ar3;
            den += __expf(a - mx);
        }
        #pragma unroll
        for (int o = 16; o; o >>= 1) den += __shfl_xor_sync(0xffffffffu, den, o);
    } else {
        for (int j = 0; j < deg; j++) {
            int s = __ldg(&g_esrc[beg + j]);
            float p = warp_dot_qk(qa, qb, s, lane);
            den += (lane == 0) ? __expf(p - mx) : 0.f;
        }
        den = __shfl_sync(0xffffffffu, den, 0);
    }
    float invden = 1.0f / (den + 1e-16f);

    float4 acca = make_float4(0.f, 0.f, 0.f, 0.f);
    float4 accb = make_float4(0.f, 0.f, 0.f, 0.f);
    for (int j = 0; j < deg; j++) {
        float a;
        if (small) {
            int slot = j >> 5;
            float av = (slot == 0) ? ar0 : (slot == 1) ? ar1 : (slot == 2) ? ar2 : ar3;
            a = __shfl_sync(0xffffffffu, av, j & 31);
        } else {
            int s0 = __ldg(&g_esrc[beg + j]);
            a = warp_dot_qk(qa, qb, s0, lane);
        }
        float attn = __expf(a - mx) * invden;
        int s = __ldg(&g_esrc[beg + j]);
        const float4* v4 = (const float4*)(g_v + (size_t)s * DD);
        float4 va = __ldg(&v4[lane]);
        float4 vb = __ldg(&v4[lane + 32]);
        acca.x += attn * va.x; acca.y += attn * va.y;
        acca.z += attn * va.z; acca.w += attn * va.w;
        accb.x += attn * vb.x; accb.y += attn * vb.y;
        accb.z += attn * vb.z; accb.w += attn * vb.w;
    }

    const float4* s4 = (const float4*)(g_s + (size_t)d * DD);
    float4 sa = s4[lane], sb = s4[lane + 32];
    float4 oa, ob;
    oa.x = acca.x + sa.x; oa.y = acca.y + sa.y;
    oa.z = acca.z + sa.z; oa.w = acca.w + sa.w;
    ob.x = accb.x + sb.x; ob.y = accb.y + sb.y;
    ob.z = accb.z + sb.z; ob.w = accb.w + sb.w;

    if (mode) {
        oa.x = fmaxf(oa.x, 0.f); oa.y = fmaxf(oa.y, 0.f);
        oa.z = fmaxf(oa.z, 0.f); oa.w = fmaxf(oa.w, 0.f);
        ob.x = fmaxf(ob.x, 0.f); ob.y = fmaxf(ob.y, 0.f);
        ob.z = fmaxf(ob.z, 0.f); ob.w = fmaxf(ob.w, 0.f);
        store_split4(d, lane * 4, oa);
        store_split4(d, 128 + lane * 4, ob);
    } else {
        float4* o4 = (float4*)(out + (size_t)d * DD);
        o4[lane] = oa;
        o4[lane + 32] = ob;
    }
}

// ---------------- launch --------------------------------------------------------
extern "C" void kernel_launch(void* const* d_in, const int* in_sizes, int n_in,
                              void* d_out, int out_size) {
    const float* x  = (const float*)d_in[0];
    const int*   ei = (const int*)d_in[1];
    const float* Wq = (const float*)d_in[2];
    const float* bq = (const float*)d_in[3];
    const float* Wk = (const float*)d_in[4];
    const float* bk = (const float*)d_in[5];
    const float* Wv = (const float*)d_in[6];
    const float* bv = (const float*)d_in[7];
    const float* Ws = (const float*)d_in[8];
    const float* bs = (const float*)d_in[9];
    float* out = (float*)d_out;

    cudaFuncSetAttribute(bf16x3_gemm_kernel,
                         cudaFuncAttributeMaxDynamicSharedMemorySize, GEMM_SMEM);

    int split_blocks = (NN * DD / 4 + 255) / 256;
    asplit_kernel<<<split_blocks, 256>>>(x);            // layer-0 input split
    wsplit_kernel<<<dim3(8, 8, 12), dim3(32, 8)>>>(Wq, Wk, Wv, Ws);

    detect_idx_kernel<<<1, 32>>>(ei);
    zero_deg_kernel<<<(NN + 255) / 256, 256>>>();
    convert_hist_kernel<<<(EE + 255) / 256, 256>>>(ei);
    scan1_kernel<<<SCAN_NB, 256>>>();
    scan2_kernel<<<1, 256>>>();
    scan3_kernel<<<SCAN_NB, 256>>>();
    scatter_kernel<<<(EE + 255) / 256, 256>>>();

    dim3 ggrid((NN + 127) / 128, 2, 4);
    int attn_blocks = (NN * 32 + 255) / 256;

    for (int l = 0; l < LL; l++) {
        size_t bo = (size_t)l * DD;
        bf16x3_gemm_kernel<<<ggrid, 256, GEMM_SMEM>>>(
            l, bq + bo, bk + bo, bv + bo, bs + bo, NN);
        dst_attn_kernel<<<attn_blocks, 256>>>(out, (l < LL - 1) ? 1 : 0);
    }
}